// round 1
// baseline (speedup 1.0000x reference)
#include <cuda_runtime.h>

// Causal linear attention (elu+1 feature map), chunked-parallel formulation.
// Shapes: q,k,v : [B=4, L=2048, H=16, D=64] fp32, out: [B, L, H, M=64] fp32.
//
// Chunking: C=128 tokens/chunk, NC=16 chunks per (b,h) sequence.
//   pass1: per-chunk KV[d][m] = sum_l kf[l,d] v[l,m], Ksum[d] = sum_l kf[l,d]
//   pass2: exclusive prefix-scan of KV / Ksum over chunks (per b,h)
//   pass3: out = causal(Qf Kf^T) V + Qf S_prev ; z = rowsum(causal A) + Qf . Ksum_prev
//          out /= (z + eps)

namespace {
constexpr int B_ = 4, L_ = 2048, H_ = 16, D_ = 64, M_ = 64;
constexpr int C_ = 128;
constexpr int NC_ = L_ / C_;   // 16
constexpr int BH_ = B_ * H_;   // 64
constexpr float EPS_ = 1e-6f;
constexpr int HD_ = H_ * D_;   // global stride between tokens
}

// Scratch (device globals; no runtime allocation allowed)
__device__ float g_KV[(size_t)BH_ * NC_ * D_ * M_];  // 16.8 MB
__device__ float g_Ks[BH_ * NC_ * D_];

__device__ __forceinline__ float fmap(float x) {
    // elu(x) + 1
    return x > 0.f ? x + 1.f : __expf(x);
}

// ---------------------------------------------------------------------------
// Pass 1: per-chunk KV^T sums. grid = BH*NC, block = 256.
// ---------------------------------------------------------------------------
__global__ __launch_bounds__(256) void la_pass1(const float* __restrict__ k,
                                                const float* __restrict__ v) {
    extern __shared__ float sm[];
    float* ks = sm;                     // [C][D+4]
    float* vs = sm + C_ * (D_ + 4);     // [C][D+4]

    const int bh = blockIdx.x / NC_;
    const int c  = blockIdx.x % NC_;
    const int b  = bh / H_, h = bh % H_;
    const int tid = threadIdx.x;
    const long gbase = (((long)b * L_ + (long)c * C_) * H_ + h) * D_;

    for (int idx = tid; idx < C_ * D_; idx += 256) {
        const int l = idx >> 6, d = idx & 63;
        const long g = gbase + (long)l * HD_ + d;
        ks[l * (D_ + 4) + d] = fmap(k[g]);
        vs[l * (D_ + 4) + d] = v[g];
    }
    __syncthreads();

    const int d  = tid >> 2;            // 0..63
    const int m0 = (tid & 3) * 16;      // 0,16,32,48
    float4 acc[4] = {};
    float ksum = 0.f;

    for (int l = 0; l < C_; l++) {
        const float kv = ks[l * (D_ + 4) + d];
        ksum += kv;
        const float4* vr = reinterpret_cast<const float4*>(&vs[l * (D_ + 4) + m0]);
        #pragma unroll
        for (int j = 0; j < 4; j++) {
            const float4 vv = vr[j];
            acc[j].x += kv * vv.x; acc[j].y += kv * vv.y;
            acc[j].z += kv * vv.z; acc[j].w += kv * vv.w;
        }
    }

    float* outp = &g_KV[((size_t)(bh * NC_ + c) * D_ + d) * M_ + m0];
    #pragma unroll
    for (int j = 0; j < 4; j++)
        reinterpret_cast<float4*>(outp)[j] = acc[j];
    if (m0 == 0) g_Ks[(bh * NC_ + c) * D_ + d] = ksum;
}

// ---------------------------------------------------------------------------
// Pass 2: exclusive prefix over chunks. grid = BH, block = 256.
// ---------------------------------------------------------------------------
__global__ __launch_bounds__(256) void la_pass2() {
    const int bh = blockIdx.x;
    for (int e = threadIdx.x; e < D_ * M_; e += 256) {
        float run = 0.f;
        #pragma unroll
        for (int c = 0; c < NC_; c++) {
            const size_t idx = (size_t)(bh * NC_ + c) * (D_ * M_) + e;
            const float t = g_KV[idx];
            g_KV[idx] = run;
            run += t;
        }
    }
    if (threadIdx.x < D_) {
        const int e = threadIdx.x;
        float run = 0.f;
        #pragma unroll
        for (int c = 0; c < NC_; c++) {
            const int idx = (bh * NC_ + c) * D_ + e;
            const float t = g_Ks[idx];
            g_Ks[idx] = run;
            run += t;
        }
    }
}

// ---------------------------------------------------------------------------
// Pass 3: intra-chunk causal attention + inter-chunk state. grid=BH*NC, 256.
// ---------------------------------------------------------------------------
__global__ __launch_bounds__(256) void la_pass3(const float* __restrict__ q,
                                                const float* __restrict__ k,
                                                const float* __restrict__ v,
                                                float* __restrict__ out) {
    extern __shared__ float sm[];
    float* qT  = sm;                          // [D][C+4]  (transposed: [d][l])
    float* kT  = qT + D_ * (C_ + 4);          // [D][C+4]
    float* AsT = kT + D_ * (C_ + 4);          // [C][C+4]  A transposed: [s][r]
    float* vs  = AsT + C_ * (C_ + 4);         // [C][M+4]
    float* Sp  = vs + C_ * (M_ + 4);          // [D][M+4]
    float* Kp  = Sp + D_ * (M_ + 4);          // [D]

    const int bh = blockIdx.x / NC_;
    const int c  = blockIdx.x % NC_;
    const int b  = bh / H_, h = bh % H_;
    const int tid = threadIdx.x;
    const long gbase = (((long)b * L_ + (long)c * C_) * H_ + h) * D_;

    for (int idx = tid; idx < C_ * D_; idx += 256) {
        const int l = idx >> 6, d = idx & 63;
        const long g = gbase + (long)l * HD_ + d;
        qT[d * (C_ + 4) + l] = fmap(q[g]);
        kT[d * (C_ + 4) + l] = fmap(k[g]);
        vs[l * (M_ + 4) + d] = v[g];
    }
    const size_t sbase = (size_t)(bh * NC_ + c) * (D_ * M_);
    for (int idx = tid; idx < D_ * M_; idx += 256)
        Sp[(idx >> 6) * (M_ + 4) + (idx & 63)] = g_KV[sbase + idx];
    if (tid < D_) Kp[tid] = g_Ks[(bh * NC_ + c) * D_ + tid];
    __syncthreads();

    // ---- Phase A: A[r][s] = qf_r . kf_s, causal mask (s<=r), store as AsT[s][r]
    {
        const int ty = tid >> 4, tx = tid & 15;
        const int r0 = ty * 8, s0 = tx * 8;
        float acc[8][8] = {};

        for (int d = 0; d < D_; d++) {
            const float* qrow = &qT[d * (C_ + 4)];
            const float* krow = &kT[d * (C_ + 4)];
            const float4 q01 = *reinterpret_cast<const float4*>(qrow + r0);
            const float4 q23 = *reinterpret_cast<const float4*>(qrow + r0 + 4);
            const float4 k01 = *reinterpret_cast<const float4*>(krow + s0);
            const float4 k23 = *reinterpret_cast<const float4*>(krow + s0 + 4);
            const float qr[8] = {q01.x, q01.y, q01.z, q01.w, q23.x, q23.y, q23.z, q23.w};
            const float kr[8] = {k01.x, k01.y, k01.z, k01.w, k23.x, k23.y, k23.z, k23.w};
            #pragma unroll
            for (int i = 0; i < 8; i++)
                #pragma unroll
                for (int j = 0; j < 8; j++)
                    acc[i][j] += qr[i] * kr[j];
        }

        #pragma unroll
        for (int j = 0; j < 8; j++) {
            const int s = s0 + j;
            float w[8];
            #pragma unroll
            for (int i = 0; i < 8; i++)
                w[i] = (s <= r0 + i) ? acc[i][j] : 0.f;
            float* dst = &AsT[s * (C_ + 4) + r0];
            *reinterpret_cast<float4*>(dst)     = make_float4(w[0], w[1], w[2], w[3]);
            *reinterpret_cast<float4*>(dst + 4) = make_float4(w[4], w[5], w[6], w[7]);
        }
    }
    __syncthreads();

    // ---- Phase B: out = A V + Qf S_prev ; z = rowsum(A) + Qf . Ksum_prev
    {
        const int ry = tid >> 4, cx = tid & 15;
        const int r0 = ry * 8, m0 = cx * 4;
        float4 o[8] = {};
        float z[8] = {};

        for (int s = 0; s < C_; s++) {
            const float* arow = &AsT[s * (C_ + 4) + r0];
            const float4 a01 = *reinterpret_cast<const float4*>(arow);
            const float4 a23 = *reinterpret_cast<const float4*>(arow + 4);
            const float4 vv  = *reinterpret_cast<const float4*>(&vs[s * (M_ + 4) + m0]);
            const float ar[8] = {a01.x, a01.y, a01.z, a01.w, a23.x, a23.y, a23.z, a23.w};
            #pragma unroll
            for (int i = 0; i < 8; i++) {
                z[i] += ar[i];
                o[i].x += ar[i] * vv.x; o[i].y += ar[i] * vv.y;
                o[i].z += ar[i] * vv.z; o[i].w += ar[i] * vv.w;
            }
        }

        for (int d = 0; d < D_; d++) {
            const float* qrow = &qT[d * (C_ + 4)];
            const float4 q01 = *reinterpret_cast<const float4*>(qrow + r0);
            const float4 q23 = *reinterpret_cast<const float4*>(qrow + r0 + 4);
            const float4 sv  = *reinterpret_cast<const float4*>(&Sp[d * (M_ + 4) + m0]);
            const float kp = Kp[d];
            const float qr[8] = {q01.x, q01.y, q01.z, q01.w, q23.x, q23.y, q23.z, q23.w};
            #pragma unroll
            for (int i = 0; i < 8; i++) {
                z[i] += qr[i] * kp;
                o[i].x += qr[i] * sv.x; o[i].y += qr[i] * sv.y;
                o[i].z += qr[i] * sv.z; o[i].w += qr[i] * sv.w;
            }
        }

        const long obase = (((long)b * L_ + (long)c * C_) * H_ + h) * M_;
        #pragma unroll
        for (int i = 0; i < 8; i++) {
            const float inv = 1.f / (z[i] + EPS_);
            const float4 w = make_float4(o[i].x * inv, o[i].y * inv,
                                         o[i].z * inv, o[i].w * inv);
            *reinterpret_cast<float4*>(&out[obase + (long)(r0 + i) * (H_ * M_) + m0]) = w;
        }
    }
}

// ---------------------------------------------------------------------------
extern "C" void kernel_launch(void* const* d_in, const int* in_sizes, int n_in,
                              void* d_out, int out_size) {
    const float* q = (const float*)d_in[0];
    const float* k = (const float*)d_in[1];
    const float* v = (const float*)d_in[2];
    float* out = (float*)d_out;

    const int smem1 = 2 * C_ * (D_ + 4) * (int)sizeof(float);                 // ~68 KB
    const int smem3 = (2 * D_ * (C_ + 4) + C_ * (C_ + 4) + C_ * (M_ + 4) +
                       D_ * (M_ + 4) + D_) * (int)sizeof(float);              // ~183 KB

    cudaFuncSetAttribute(la_pass1, cudaFuncAttributeMaxDynamicSharedMemorySize, smem1);
    cudaFuncSetAttribute(la_pass3, cudaFuncAttributeMaxDynamicSharedMemorySize, smem3);

    la_pass1<<<BH_ * NC_, 256, smem1>>>(k, v);
    la_pass2<<<BH_, 256>>>();
    la_pass3<<<BH_ * NC_, 256, smem3>>>(q, k, v, out);
}

// round 3
// speedup vs baseline: 1.9118x; 1.9118x over previous
#include <cuda_runtime.h>
#include <cuda_bf16.h>
#include <cstdint>

// Causal linear attention (elu+1), chunked, mma.sync bf16 hi/lo (fp32-emulated).
// q,k,v: [B=4, L=2048, H=16, D=64] fp32 -> out [B,L,H,64] fp32.

namespace {
constexpr int B_ = 4, L_ = 2048, H_ = 16, D_ = 64, M_ = 64;
constexpr int C_ = 128;
constexpr int NC_ = L_ / C_;   // 16
constexpr int BH_ = B_ * H_;   // 64
constexpr float EPS_ = 1e-6f;
constexpr int HD_ = H_ * D_;   // 1024
constexpr int PS_ = 72;        // padded row stride (bf16 elems) -> 144B, conflict-free LDSM

constexpr int SZT = C_ * PS_ * 2;   // 18432 B per 128-row bf16 tile
constexpr int SZS = 64 * PS_ * 2;   // 9216 B per 64-row bf16 tile
constexpr int OFF_QH = 0;
constexpr int OFF_QL = OFF_QH + SZT;
constexpr int OFF_KH = OFF_QL + SZT;
constexpr int OFF_KL = OFF_KH + SZT;
constexpr int OFF_VH = OFF_KL + SZT;
constexpr int OFF_VL = OFF_VH + SZT;
constexpr int OFF_SH = OFF_VL + SZT;
constexpr int OFF_SL = OFF_SH + SZS;
constexpr int OFF_KP  = OFF_SL + SZS;     // 64 f32
constexpr int OFF_Z   = OFF_KP + 256;     // 128 f32
constexpr int OFF_QDK = OFF_Z + 512;      // 128 f32
constexpr int SMEM3   = OFF_QDK + 512;    // ~130.3 KB
}

__device__ float g_KV[(size_t)BH_ * NC_ * D_ * M_];
__device__ float g_Ks[BH_ * NC_ * D_];

__device__ __forceinline__ float fmap(float x) { return x > 0.f ? x + 1.f : __expf(x); }

__device__ __forceinline__ uint32_t smem_u32(const void* p) {
    uint32_t a;
    asm("{ .reg .u64 t; cvta.to.shared.u64 t, %1; cvt.u32.u64 %0, t; }" : "=r"(a) : "l"(p));
    return a;
}
__device__ __forceinline__ uint32_t pack_bf2(__nv_bfloat16 a, __nv_bfloat16 b) {
    __nv_bfloat162 t = __halves2bfloat162(a, b);
    return *reinterpret_cast<uint32_t*>(&t);
}
// split two floats -> packed bf16x2 hi and lo
__device__ __forceinline__ void split2(float f0, float f1, uint32_t& h, uint32_t& l) {
    __nv_bfloat16 h0 = __float2bfloat16(f0), h1 = __float2bfloat16(f1);
    __nv_bfloat16 l0 = __float2bfloat16(f0 - __bfloat162float(h0));
    __nv_bfloat16 l1 = __float2bfloat16(f1 - __bfloat162float(h1));
    h = pack_bf2(h0, h1);
    l = pack_bf2(l0, l1);
}
__device__ __forceinline__ void split4(const float* f, uint2& hi, uint2& lo) {
    split2(f[0], f[1], hi.x, lo.x);
    split2(f[2], f[3], hi.y, lo.y);
}

__device__ __forceinline__ void ldsm_x4(uint32_t* r, uint32_t addr) {
    asm volatile("ldmatrix.sync.aligned.m8n8.x4.shared.b16 {%0,%1,%2,%3}, [%4];"
                 : "=r"(r[0]), "=r"(r[1]), "=r"(r[2]), "=r"(r[3]) : "r"(addr));
}
__device__ __forceinline__ void ldsm_x2(uint32_t& b0, uint32_t& b1, uint32_t addr) {
    asm volatile("ldmatrix.sync.aligned.m8n8.x2.shared.b16 {%0,%1}, [%2];"
                 : "=r"(b0), "=r"(b1) : "r"(addr));
}
__device__ __forceinline__ void ldsm_x2t(uint32_t& b0, uint32_t& b1, uint32_t addr) {
    asm volatile("ldmatrix.sync.aligned.m8n8.x2.trans.shared.b16 {%0,%1}, [%2];"
                 : "=r"(b0), "=r"(b1) : "r"(addr));
}
__device__ __forceinline__ void mma16816(float* c, const uint32_t* a, uint32_t b0, uint32_t b1) {
    asm volatile("mma.sync.aligned.m16n8k16.row.col.f32.bf16.bf16.f32 "
                 "{%0,%1,%2,%3}, {%4,%5,%6,%7}, {%8,%9}, {%0,%1,%2,%3};"
                 : "+f"(c[0]), "+f"(c[1]), "+f"(c[2]), "+f"(c[3])
                 : "r"(a[0]), "r"(a[1]), "r"(a[2]), "r"(a[3]), "r"(b0), "r"(b1));
}

// ---------------------------------------------------------------------------
// Pass 1: per-chunk KV^T (register-tiled SIMT). grid = BH*NC, block = 256.
// ---------------------------------------------------------------------------
__global__ __launch_bounds__(256) void la_pass1(const float* __restrict__ k,
                                                const float* __restrict__ v) {
    extern __shared__ float sm1[];
    float* ks = sm1;                   // [C][68]
    float* vs = sm1 + C_ * 68;         // [C][68]

    const int blk = blockIdx.x;
    const int bh = blk / NC_, c = blk % NC_;
    const int b = bh / H_, h = bh % H_;
    const int tid = threadIdx.x;
    const long gbase = (((long)b * L_ + (long)c * C_) * H_ + h) * D_;

    for (int i = tid; i < C_ * 16; i += 256) {
        const int l = i >> 4, d4 = (i & 15) * 4;
        const float4 kk = *reinterpret_cast<const float4*>(&k[gbase + (long)l * HD_ + d4]);
        const float4 vv = *reinterpret_cast<const float4*>(&v[gbase + (long)l * HD_ + d4]);
        *reinterpret_cast<float4*>(&ks[l * 68 + d4]) =
            make_float4(fmap(kk.x), fmap(kk.y), fmap(kk.z), fmap(kk.w));
        *reinterpret_cast<float4*>(&vs[l * 68 + d4]) = vv;
    }
    __syncthreads();

    const int d0 = (tid >> 4) * 4;
    const int m0 = (tid & 15) * 4;
    float4 acc[4] = {};
    float4 ksum = make_float4(0.f, 0.f, 0.f, 0.f);

#pragma unroll 2
    for (int l = 0; l < C_; l++) {
        const float4 kk = *reinterpret_cast<const float4*>(&ks[l * 68 + d0]);
        const float4 vv = *reinterpret_cast<const float4*>(&vs[l * 68 + m0]);
        ksum.x += kk.x; ksum.y += kk.y; ksum.z += kk.z; ksum.w += kk.w;
        acc[0].x += kk.x * vv.x; acc[0].y += kk.x * vv.y; acc[0].z += kk.x * vv.z; acc[0].w += kk.x * vv.w;
        acc[1].x += kk.y * vv.x; acc[1].y += kk.y * vv.y; acc[1].z += kk.y * vv.z; acc[1].w += kk.y * vv.w;
        acc[2].x += kk.z * vv.x; acc[2].y += kk.z * vv.y; acc[2].z += kk.z * vv.z; acc[2].w += kk.z * vv.w;
        acc[3].x += kk.w * vv.x; acc[3].y += kk.w * vv.y; acc[3].z += kk.w * vv.z; acc[3].w += kk.w * vv.w;
    }

    float* outp = &g_KV[((size_t)blk * D_ + d0) * M_ + m0];
#pragma unroll
    for (int i = 0; i < 4; i++)
        *reinterpret_cast<float4*>(outp + (size_t)i * M_) = acc[i];
    if (m0 == 0)
        *reinterpret_cast<float4*>(&g_Ks[blk * D_ + d0]) = ksum;
}

// ---------------------------------------------------------------------------
// Pass 2: exclusive prefix over chunks. grid = BH*8, block = 256.
// ---------------------------------------------------------------------------
__global__ __launch_bounds__(256) void la_pass2() {
    const int bh = blockIdx.x >> 3;
    const int sub = blockIdx.x & 7;
    const int e0 = sub * 512;
    for (int e = e0 + threadIdx.x; e < e0 + 512; e += 256) {
        float run = 0.f;
#pragma unroll
        for (int c = 0; c < NC_; c++) {
            const size_t idx = (size_t)(bh * NC_ + c) * (D_ * M_) + e;
            const float t = g_KV[idx];
            g_KV[idx] = run;
            run += t;
        }
    }
    if (sub == 0 && threadIdx.x < D_) {
        const int e = threadIdx.x;
        float run = 0.f;
#pragma unroll
        for (int c = 0; c < NC_; c++) {
            const int idx = (bh * NC_ + c) * D_ + e;
            const float t = g_Ks[idx];
            g_Ks[idx] = run;
            run += t;
        }
    }
}

// ---------------------------------------------------------------------------
// Pass 3: mma.sync chunk attention. grid = BH*NC, block = 256 (8 warps).
// Warp w owns rows [16w, 16w+16).
// ---------------------------------------------------------------------------
__global__ __launch_bounds__(256) void la_pass3(const float* __restrict__ q,
                                                const float* __restrict__ k,
                                                const float* __restrict__ v,
                                                float* __restrict__ out) {
    extern __shared__ char smem[];
    const uint32_t sb = smem_u32(smem);
    const int tid = threadIdx.x;
    const int wid = tid >> 5, lane = tid & 31;

    const int blk = blockIdx.x;
    const int bh = blk / NC_, c = blk % NC_;
    const int b = bh / H_, h = bh % H_;
    const long gbase = (((long)b * L_ + (long)c * C_) * H_ + h) * D_;

    // ---- P0: load chunk, fmap, hi/lo split -> padded smem tiles ------------
    for (int i = tid; i < C_ * 16; i += 256) {
        const int l = i >> 4, d4 = (i & 15) * 4;
        const long g = gbase + (long)l * HD_ + d4;
        const int so = (l * PS_ + d4) * 2;
        uint2 hi, lo;

        const float4 qv = *reinterpret_cast<const float4*>(&q[g]);
        float fq[4] = {fmap(qv.x), fmap(qv.y), fmap(qv.z), fmap(qv.w)};
        split4(fq, hi, lo);
        *reinterpret_cast<uint2*>(smem + OFF_QH + so) = hi;
        *reinterpret_cast<uint2*>(smem + OFF_QL + so) = lo;

        const float4 kv = *reinterpret_cast<const float4*>(&k[g]);
        float fk[4] = {fmap(kv.x), fmap(kv.y), fmap(kv.z), fmap(kv.w)};
        split4(fk, hi, lo);
        *reinterpret_cast<uint2*>(smem + OFF_KH + so) = hi;
        *reinterpret_cast<uint2*>(smem + OFF_KL + so) = lo;

        const float4 vv = *reinterpret_cast<const float4*>(&v[g]);
        float fv[4] = {vv.x, vv.y, vv.z, vv.w};
        split4(fv, hi, lo);
        *reinterpret_cast<uint2*>(smem + OFF_VH + so) = hi;
        *reinterpret_cast<uint2*>(smem + OFF_VL + so) = lo;
    }
    {
        const size_t spb = (size_t)blk * (D_ * M_);
        for (int i = tid; i < D_ * 16; i += 256) {
            const int d = i >> 4, m4 = (i & 15) * 4;
            const float4 sv = *reinterpret_cast<const float4*>(&g_KV[spb + (size_t)d * M_ + m4]);
            float fs[4] = {sv.x, sv.y, sv.z, sv.w};
            uint2 hi, lo;
            split4(fs, hi, lo);
            const int so = (d * PS_ + m4) * 2;
            *reinterpret_cast<uint2*>(smem + OFF_SH + so) = hi;
            *reinterpret_cast<uint2*>(smem + OFF_SL + so) = lo;
        }
        if (tid < D_)
            reinterpret_cast<float*>(smem + OFF_KP)[tid] = g_Ks[blk * D_ + tid];
    }
    __syncthreads();

    const int w = wid, r0 = w * 16;
    const int g4 = lane >> 2, t4 = lane & 3;
    float* Zs  = reinterpret_cast<float*>(smem + OFF_Z);
    float* QDs = reinterpret_cast<float*>(smem + OFF_QDK);

    // ldmatrix address lane patterns
    const int arow = (lane & 7) + ((lane >> 3) & 1) * 8;   // x4 row
    const int acolb = (lane >> 4) * 8;                     // x4 col block
    const int brow = lane & 7;                             // x2 row
    const int bcolb = ((lane >> 3) & 1) * 8;               // x2 col block
    const int vrow = (lane & 7) + ((lane >> 3) & 1) * 8;   // x2.trans k-row

    // ---- Phase A: A = Qf Kf^T (causal tiles only) ---------------------------
    uint32_t qa[2][4][4];
#pragma unroll
    for (int kt = 0; kt < 4; kt++) {
        const uint32_t aH = sb + OFF_QH + (uint32_t)(((r0 + arow) * PS_ + kt * 16 + acolb) * 2);
        ldsm_x4(qa[0][kt], aH);
        ldsm_x4(qa[1][kt], aH + (OFF_QL - OFF_QH));
    }

    const int ntiles = 2 * w + 2;
    float acc[16][4];
#pragma unroll
    for (int j = 0; j < 16; j++)
#pragma unroll
        for (int t = 0; t < 4; t++) acc[j][t] = 0.f;

#pragma unroll
    for (int j = 0; j < 16; j++) {
        if (j < ntiles) {
#pragma unroll
            for (int kt = 0; kt < 4; kt++) {
                const uint32_t adr = sb + OFF_KH +
                    (uint32_t)(((8 * j + brow) * PS_ + kt * 16 + bcolb) * 2);
                uint32_t bh0, bh1, bl0, bl1;
                ldsm_x2(bh0, bh1, adr);
                ldsm_x2(bl0, bl1, adr + (OFF_KL - OFF_KH));
                mma16816(acc[j], qa[0][kt], bh0, bh1);
                mma16816(acc[j], qa[0][kt], bl0, bl1);
                mma16816(acc[j], qa[1][kt], bh0, bh1);
            }
        }
    }

    // mask diagonal tiles, rowsum, convert C-frags -> bf16 hi/lo A-frags
    const int m0r = r0 + g4, m1r = m0r + 8;
    float z0 = 0.f, z1 = 0.f;
    uint32_t aB[2][8][4];
#pragma unroll
    for (int j = 0; j < 16; j++) {
        if (j < ntiles) {
            float c0 = acc[j][0], c1 = acc[j][1], c2 = acc[j][2], c3 = acc[j][3];
            if (j >= 2 * w) {
                const int n0 = 8 * j + 2 * t4;
                c0 = (n0     <= m0r) ? c0 : 0.f;
                c1 = (n0 + 1 <= m0r) ? c1 : 0.f;
                c2 = (n0     <= m1r) ? c2 : 0.f;
                c3 = (n0 + 1 <= m1r) ? c3 : 0.f;
            }
            z0 += c0 + c1;
            z1 += c2 + c3;
            uint32_t h01, l01, h23, l23;
            split2(c0, c1, h01, l01);
            split2(c2, c3, h23, l23);
            const int kt2 = j >> 1, p = (j & 1) * 2;
            aB[0][kt2][p] = h01; aB[0][kt2][p + 1] = h23;
            aB[1][kt2][p] = l01; aB[1][kt2][p + 1] = l23;
        }
    }
    z0 += __shfl_xor_sync(0xffffffffu, z0, 1);
    z0 += __shfl_xor_sync(0xffffffffu, z0, 2);
    z1 += __shfl_xor_sync(0xffffffffu, z1, 1);
    z1 += __shfl_xor_sync(0xffffffffu, z1, 2);
    if (t4 == 0) { Zs[m0r] = z0; Zs[m1r] = z1; }

    // ---- qdk[r] = Qf[r] . Ksum_prev (warp-local rows) -----------------------
    {
        const int r = r0 + (lane >> 1), half = lane & 1;
        const float* kp = reinterpret_cast<const float*>(smem + OFF_KP);
        float s = 0.f;
#pragma unroll
        for (int d = half * 32; d < half * 32 + 32; d += 2) {
            const int so = (r * PS_ + d) * 2;
            const __nv_bfloat162 hh = *reinterpret_cast<const __nv_bfloat162*>(smem + OFF_QH + so);
            const __nv_bfloat162 ll = *reinterpret_cast<const __nv_bfloat162*>(smem + OFF_QL + so);
            s += (__bfloat162float(hh.x) + __bfloat162float(ll.x)) * kp[d]
               + (__bfloat162float(hh.y) + __bfloat162float(ll.y)) * kp[d + 1];
        }
        s += __shfl_xor_sync(0xffffffffu, s, 1);
        if (!half) QDs[r] = s;
    }

    // ---- Phase B: O = A V (K truncated by causality) ------------------------
    float o[8][4];
#pragma unroll
    for (int nt = 0; nt < 8; nt++)
#pragma unroll
        for (int t = 0; t < 4; t++) o[nt][t] = 0.f;

#pragma unroll
    for (int kt = 0; kt < 8; kt++) {
        if (kt <= w) {
#pragma unroll
            for (int nt = 0; nt < 8; nt++) {
                const uint32_t adr = sb + OFF_VH +
                    (uint32_t)(((kt * 16 + vrow) * PS_ + nt * 8) * 2);
                uint32_t bh0, bh1, bl0, bl1;
                ldsm_x2t(bh0, bh1, adr);
                ldsm_x2t(bl0, bl1, adr + (OFF_VL - OFF_VH));
                mma16816(o[nt], aB[0][kt], bh0, bh1);
                mma16816(o[nt], aB[0][kt], bl0, bl1);
                mma16816(o[nt], aB[1][kt], bh0, bh1);
            }
        }
    }

    // ---- Phase C: O += Qf S_prev --------------------------------------------
#pragma unroll
    for (int kt = 0; kt < 4; kt++) {
        uint32_t qh[4], ql[4];
        const uint32_t aH = sb + OFF_QH + (uint32_t)(((r0 + arow) * PS_ + kt * 16 + acolb) * 2);
        ldsm_x4(qh, aH);
        ldsm_x4(ql, aH + (OFF_QL - OFF_QH));
#pragma unroll
        for (int nt = 0; nt < 8; nt++) {
            const uint32_t adr = sb + OFF_SH +
                (uint32_t)(((kt * 16 + vrow) * PS_ + nt * 8) * 2);
            uint32_t bh0, bh1, bl0, bl1;
            ldsm_x2t(bh0, bh1, adr);
            ldsm_x2t(bl0, bl1, adr + (OFF_SL - OFF_SH));
            mma16816(o[nt], qh, bh0, bh1);
            mma16816(o[nt], qh, bl0, bl1);
            mma16816(o[nt], ql, bh0, bh1);
        }
    }

    __syncwarp();

    // ---- epilogue: divide by z, store ---------------------------------------
    {
        const float za = Zs[m0r] + QDs[m0r] + EPS_;
        const float zb = Zs[m1r] + QDs[m1r] + EPS_;
        const float inva = 1.f / za, invb = 1.f / zb;
        const long ob0 = gbase + (long)m0r * HD_;
        const long ob1 = gbase + (long)m1r * HD_;
#pragma unroll
        for (int nt = 0; nt < 8; nt++) {
            const int n = nt * 8 + 2 * t4;
            *reinterpret_cast<float2*>(&out[ob0 + n]) =
                make_float2(o[nt][0] * inva, o[nt][1] * inva);
            *reinterpret_cast<float2*>(&out[ob1 + n]) =
                make_float2(o[nt][2] * invb, o[nt][3] * invb);
        }
    }
}

// ---------------------------------------------------------------------------
extern "C" void kernel_launch(void* const* d_in, const int* in_sizes, int n_in,
                              void* d_out, int out_size) {
    const float* q = (const float*)d_in[0];
    const float* k = (const float*)d_in[1];
    const float* v = (const float*)d_in[2];
    float* out = (float*)d_out;

    const int smem1 = 2 * C_ * 68 * (int)sizeof(float);

    cudaFuncSetAttribute(la_pass1, cudaFuncAttributeMaxDynamicSharedMemorySize, smem1);
    cudaFuncSetAttribute(la_pass3, cudaFuncAttributeMaxDynamicSharedMemorySize, SMEM3);

    la_pass1<<<BH_ * NC_, 256, smem1>>>(k, v);
    la_pass2<<<BH_ * 8, 256>>>();
    la_pass3<<<BH_ * NC_, 256, SMEM3>>>(q, k, v, out);
}

// round 4
// speedup vs baseline: 2.1152x; 1.1064x over previous
#include <cuda_runtime.h>
#include <cuda_bf16.h>
#include <cstdint>

// Causal linear attention (elu+1), chunked, mma.sync bf16 hi/lo (fp32-emulated).
// q,k,v: [B=4, L=2048, H=16, D=64] fp32 -> out [B,L,H,64] fp32.

namespace {
constexpr int B_ = 4, L_ = 2048, H_ = 16, D_ = 64, M_ = 64;
constexpr int C_ = 128;
constexpr int NC_ = L_ / C_;   // 16
constexpr int BH_ = B_ * H_;   // 64
constexpr float EPS_ = 1e-6f;
constexpr int HD_ = H_ * D_;   // 1024
constexpr int PS_ = 72;        // padded row stride (bf16) -> 144B, conflict-free LDSM

constexpr int SZT = C_ * PS_ * 2;   // 18432 B per 128-row bf16 tile
constexpr int SZS = 64 * PS_ * 2;   // 9216 B per 64-row bf16 tile

// pass3 smem
constexpr int OFF_QH = 0;
constexpr int OFF_QL = OFF_QH + SZT;
constexpr int OFF_KH = OFF_QL + SZT;
constexpr int OFF_KL = OFF_KH + SZT;
constexpr int OFF_VH = OFF_KL + SZT;
constexpr int OFF_VL = OFF_VH + SZT;
constexpr int OFF_SH = OFF_VL + SZT;
constexpr int OFF_SL = OFF_SH + SZS;
constexpr int SMEM3  = OFF_SL + SZS;       // 129,024 B

// pass1 smem
constexpr int P1_KH = 0;
constexpr int P1_KL = P1_KH + SZT;
constexpr int P1_VH = P1_KL + SZT;
constexpr int P1_VL = P1_VH + SZT;
constexpr int P1_RED = P1_VL + SZT;        // 4*64 floats
constexpr int SMEM1  = P1_RED + 1024;      // 74,752 B
}

__device__ float g_KV[(size_t)BH_ * NC_ * D_ * M_];
__device__ float g_Ks[BH_ * NC_ * D_];

__device__ __forceinline__ float fmap(float x) { return x > 0.f ? x + 1.f : __expf(x); }

__device__ __forceinline__ uint32_t smem_u32(const void* p) {
    uint32_t a;
    asm("{ .reg .u64 t; cvta.to.shared.u64 t, %1; cvt.u32.u64 %0, t; }" : "=r"(a) : "l"(p));
    return a;
}
// truncation-based hi/lo split of a float pair -> packed bf16x2 (lo lane = f0)
__device__ __forceinline__ void tsplit2(float f0, float f1, uint32_t& h, uint32_t& l) {
    const uint32_t u0 = __float_as_uint(f0), u1 = __float_as_uint(f1);
    asm("prmt.b32 %0, %1, %2, 0x7632;" : "=r"(h) : "r"(u0), "r"(u1));
    const float r0 = f0 - __uint_as_float(u0 & 0xffff0000u);
    const float r1 = f1 - __uint_as_float(u1 & 0xffff0000u);
    asm("cvt.rn.bf16x2.f32 %0, %1, %2;" : "=r"(l) : "f"(r1), "f"(r0));
}
__device__ __forceinline__ void tsplit4(const float* f, uint2& hi, uint2& lo) {
    tsplit2(f[0], f[1], hi.x, lo.x);
    tsplit2(f[2], f[3], hi.y, lo.y);
}

__device__ __forceinline__ void ldsm_x4(uint32_t* r, uint32_t addr) {
    asm volatile("ldmatrix.sync.aligned.m8n8.x4.shared.b16 {%0,%1,%2,%3}, [%4];"
                 : "=r"(r[0]), "=r"(r[1]), "=r"(r[2]), "=r"(r[3]) : "r"(addr));
}
__device__ __forceinline__ void ldsm_x4t(uint32_t* r, uint32_t addr) {
    asm volatile("ldmatrix.sync.aligned.m8n8.x4.trans.shared.b16 {%0,%1,%2,%3}, [%4];"
                 : "=r"(r[0]), "=r"(r[1]), "=r"(r[2]), "=r"(r[3]) : "r"(addr));
}
__device__ __forceinline__ void ldsm_x2(uint32_t& b0, uint32_t& b1, uint32_t addr) {
    asm volatile("ldmatrix.sync.aligned.m8n8.x2.shared.b16 {%0,%1}, [%2];"
                 : "=r"(b0), "=r"(b1) : "r"(addr));
}
__device__ __forceinline__ void ldsm_x2t(uint32_t& b0, uint32_t& b1, uint32_t addr) {
    asm volatile("ldmatrix.sync.aligned.m8n8.x2.trans.shared.b16 {%0,%1}, [%2];"
                 : "=r"(b0), "=r"(b1) : "r"(addr));
}
__device__ __forceinline__ void mma16816(float* c, const uint32_t* a, uint32_t b0, uint32_t b1) {
    asm volatile("mma.sync.aligned.m16n8k16.row.col.f32.bf16.bf16.f32 "
                 "{%0,%1,%2,%3}, {%4,%5,%6,%7}, {%8,%9}, {%0,%1,%2,%3};"
                 : "+f"(c[0]), "+f"(c[1]), "+f"(c[2]), "+f"(c[3])
                 : "r"(a[0]), "r"(a[1]), "r"(a[2]), "r"(a[3]), "r"(b0), "r"(b1));
}

// ---------------------------------------------------------------------------
// Pass 1: per-chunk KV = Kf^T V via mma.sync. grid = BH*NC, block = 256.
// ---------------------------------------------------------------------------
__global__ __launch_bounds__(256) void la_pass1(const float* __restrict__ k,
                                                const float* __restrict__ v) {
    extern __shared__ char smem[];
    const uint32_t sb = smem_u32(smem);
    const int tid = threadIdx.x;
    const int wid = tid >> 5, lane = tid & 31;

    const int blk = blockIdx.x;
    const int bh = blk / NC_, c = blk % NC_;
    const int b = bh / H_, h = bh % H_;
    const long gbase = (((long)b * L_ + (long)c * C_) * H_ + h) * D_;

    // P0: load k,v chunk; fmap(k); trunc-split -> padded smem tiles
    for (int i = tid; i < C_ * 16; i += 256) {
        const int l = i >> 4, d4 = (i & 15) * 4;
        const long g = gbase + (long)l * HD_ + d4;
        const int so = (l * PS_ + d4) * 2;
        uint2 hi, lo;

        const float4 kk = *reinterpret_cast<const float4*>(&k[g]);
        float fk[4] = {fmap(kk.x), fmap(kk.y), fmap(kk.z), fmap(kk.w)};
        tsplit4(fk, hi, lo);
        *reinterpret_cast<uint2*>(smem + P1_KH + so) = hi;
        *reinterpret_cast<uint2*>(smem + P1_KL + so) = lo;

        const float4 vv = *reinterpret_cast<const float4*>(&v[g]);
        float fv[4] = {vv.x, vv.y, vv.z, vv.w};
        tsplit4(fv, hi, lo);
        *reinterpret_cast<uint2*>(smem + P1_VH + so) = hi;
        *reinterpret_cast<uint2*>(smem + P1_VL + so) = lo;
    }
    __syncthreads();

    // MMA: warp wid owns n-tile (m columns 8*wid..8*wid+8); M=64 (d), K=128 (l)
    const int g4 = lane >> 2, t4 = lane & 3;
    const int vrow = (lane & 7) + ((lane >> 3) & 1) * 8;           // B x2.trans row
    const int asrow = (lane & 7) + ((lane >> 4) & 1) * 8;          // A x4.trans src row
    const int ascol = ((lane >> 3) & 1) * 8;                       // A x4.trans src col

    float acc[4][4];
#pragma unroll
    for (int mt = 0; mt < 4; mt++)
#pragma unroll
        for (int t = 0; t < 4; t++) acc[mt][t] = 0.f;

#pragma unroll
    for (int kt = 0; kt < 8; kt++) {
        uint32_t bh0, bh1, bl0, bl1;
        const uint32_t adrV = sb + P1_VH + (uint32_t)(((kt * 16 + vrow) * PS_ + wid * 8) * 2);
        ldsm_x2t(bh0, bh1, adrV);
        ldsm_x2t(bl0, bl1, adrV + (P1_VL - P1_VH));
#pragma unroll
        for (int mt = 0; mt < 4; mt++) {
            uint32_t ah[4], al[4];
            const uint32_t adrK = sb + P1_KH +
                (uint32_t)(((kt * 16 + asrow) * PS_ + mt * 16 + ascol) * 2);
            ldsm_x4t(ah, adrK);
            ldsm_x4t(al, adrK + (P1_KL - P1_KH));
            mma16816(acc[mt], ah, bh0, bh1);
            mma16816(acc[mt], ah, bl0, bl1);
            mma16816(acc[mt], al, bh0, bh1);
        }
    }

    // write KV [d][m] fp32
    {
        const size_t ob = (size_t)blk * (D_ * M_);
        const int m = wid * 8 + 2 * t4;
#pragma unroll
        for (int mt = 0; mt < 4; mt++) {
            const int d0 = mt * 16 + g4;
            *reinterpret_cast<float2*>(&g_KV[ob + (size_t)d0 * M_ + m]) =
                make_float2(acc[mt][0], acc[mt][1]);
            *reinterpret_cast<float2*>(&g_KV[ob + (size_t)(d0 + 8) * M_ + m]) =
                make_float2(acc[mt][2], acc[mt][3]);
        }
    }

    // Ksum[d] = sum_l Kf[l][d]
    {
        float* red = reinterpret_cast<float*>(smem + P1_RED);
        const int part = tid >> 6, d = tid & 63;
        const __nv_bfloat16* kh = reinterpret_cast<const __nv_bfloat16*>(smem + P1_KH);
        const __nv_bfloat16* kl = reinterpret_cast<const __nv_bfloat16*>(smem + P1_KL);
        float s = 0.f;
#pragma unroll 4
        for (int l = part * 32; l < part * 32 + 32; l++) {
            const int so = l * PS_ + d;
            s += __bfloat162float(kh[so]) + __bfloat162float(kl[so]);
        }
        red[part * 64 + d] = s;
        __syncthreads();
        if (tid < 64)
            g_Ks[blk * D_ + tid] = red[tid] + red[64 + tid] + red[128 + tid] + red[192 + tid];
    }
}

// ---------------------------------------------------------------------------
// Pass 2: exclusive prefix over chunks. grid = BH*8, block = 256.
// ---------------------------------------------------------------------------
__global__ __launch_bounds__(256) void la_pass2() {
    const int bh = blockIdx.x >> 3;
    const int sub = blockIdx.x & 7;
    const int e0 = sub * 512;
    for (int e = e0 + threadIdx.x; e < e0 + 512; e += 256) {
        float run = 0.f;
#pragma unroll
        for (int c = 0; c < NC_; c++) {
            const size_t idx = (size_t)(bh * NC_ + c) * (D_ * M_) + e;
            const float t = g_KV[idx];
            g_KV[idx] = run;
            run += t;
        }
    }
    if (sub == 0 && threadIdx.x < D_) {
        const int e = threadIdx.x;
        float run = 0.f;
#pragma unroll
        for (int c = 0; c < NC_; c++) {
            const int idx = (bh * NC_ + c) * D_ + e;
            const float t = g_Ks[idx];
            g_Ks[idx] = run;
            run += t;
        }
    }
}

// ---------------------------------------------------------------------------
// Pass 3: mma.sync chunk attention. grid = BH*NC, block = 256 (8 warps).
// Warp w owns row-tile rt = (w<4 ? w : 11-w) -> per-SMSP work balanced.
// ---------------------------------------------------------------------------
__global__ __launch_bounds__(256) void la_pass3(const float* __restrict__ q,
                                                const float* __restrict__ k,
                                                const float* __restrict__ v,
                                                float* __restrict__ out) {
    extern __shared__ char smem[];
    const uint32_t sb = smem_u32(smem);
    const int tid = threadIdx.x;
    const int wid = tid >> 5, lane = tid & 31;

    const int blk = blockIdx.x;
    const int bh = blk / NC_, c = blk % NC_;
    const int b = bh / H_, h = bh % H_;
    const long gbase = (((long)b * L_ + (long)c * C_) * H_ + h) * D_;

    // ---- P0: load chunk, fmap, trunc-split -> padded smem tiles ------------
    for (int i = tid; i < C_ * 16; i += 256) {
        const int l = i >> 4, d4 = (i & 15) * 4;
        const long g = gbase + (long)l * HD_ + d4;
        const int so = (l * PS_ + d4) * 2;
        uint2 hi, lo;

        const float4 qv = *reinterpret_cast<const float4*>(&q[g]);
        float fq[4] = {fmap(qv.x), fmap(qv.y), fmap(qv.z), fmap(qv.w)};
        tsplit4(fq, hi, lo);
        *reinterpret_cast<uint2*>(smem + OFF_QH + so) = hi;
        *reinterpret_cast<uint2*>(smem + OFF_QL + so) = lo;

        const float4 kv = *reinterpret_cast<const float4*>(&k[g]);
        float fk[4] = {fmap(kv.x), fmap(kv.y), fmap(kv.z), fmap(kv.w)};
        tsplit4(fk, hi, lo);
        *reinterpret_cast<uint2*>(smem + OFF_KH + so) = hi;
        *reinterpret_cast<uint2*>(smem + OFF_KL + so) = lo;

        const float4 vv = *reinterpret_cast<const float4*>(&v[g]);
        float fv[4] = {vv.x, vv.y, vv.z, vv.w};
        tsplit4(fv, hi, lo);
        *reinterpret_cast<uint2*>(smem + OFF_VH + so) = hi;
        *reinterpret_cast<uint2*>(smem + OFF_VL + so) = lo;
    }
    // S_prev tile [64][64] + Ksum_prev embedded at column 64 (cols 65-71 zero)
    {
        const size_t spb = (size_t)blk * (D_ * M_);
        for (int i = tid; i < D_ * 16; i += 256) {
            const int d = i >> 4, m4 = (i & 15) * 4;
            const float4 sv = *reinterpret_cast<const float4*>(&g_KV[spb + (size_t)d * M_ + m4]);
            float fs[4] = {sv.x, sv.y, sv.z, sv.w};
            uint2 hi, lo;
            tsplit4(fs, hi, lo);
            const int so = (d * PS_ + m4) * 2;
            *reinterpret_cast<uint2*>(smem + OFF_SH + so) = hi;
            *reinterpret_cast<uint2*>(smem + OFF_SL + so) = lo;
        }
        if (tid < D_) {
            const float ks = g_Ks[blk * D_ + tid];
            uint32_t h, l;
            tsplit2(ks, 0.f, h, l);
            const int so = (tid * PS_ + 64) * 2;
            *reinterpret_cast<uint2*>(smem + OFF_SH + so) = make_uint2(h, 0u);
            *reinterpret_cast<uint2*>(smem + OFF_SH + so + 8) = make_uint2(0u, 0u);
            *reinterpret_cast<uint2*>(smem + OFF_SL + so) = make_uint2(l, 0u);
            *reinterpret_cast<uint2*>(smem + OFF_SL + so + 8) = make_uint2(0u, 0u);
        }
    }
    __syncthreads();

    const int rt = (wid < 4) ? wid : 11 - wid;    // SMSP-balanced row-tile
    const int r0 = rt * 16;
    const int g4 = lane >> 2, t4 = lane & 3;

    const int arow = (lane & 7) + ((lane >> 3) & 1) * 8;   // x4 row
    const int acolb = (lane >> 4) * 8;                     // x4 col block
    const int brow = lane & 7;                             // x2 row
    const int bcolb = ((lane >> 3) & 1) * 8;               // x2 col block
    const int vrow = (lane & 7) + ((lane >> 3) & 1) * 8;   // x2.trans k-row

    // ---- Phase A: A = Qf Kf^T (causal tiles only) ---------------------------
    uint32_t qa[2][4][4];
#pragma unroll
    for (int kt = 0; kt < 4; kt++) {
        const uint32_t aH = sb + OFF_QH + (uint32_t)(((r0 + arow) * PS_ + kt * 16 + acolb) * 2);
        ldsm_x4(qa[0][kt], aH);
        ldsm_x4(qa[1][kt], aH + (OFF_QL - OFF_QH));
    }

    const int ntiles = 2 * rt + 2;
    float acc[16][4];
#pragma unroll
    for (int j = 0; j < 16; j++)
#pragma unroll
        for (int t = 0; t < 4; t++) acc[j][t] = 0.f;

#pragma unroll
    for (int j = 0; j < 16; j++) {
        if (j < ntiles) {
#pragma unroll
            for (int kt = 0; kt < 4; kt++) {
                const uint32_t adr = sb + OFF_KH +
                    (uint32_t)(((8 * j + brow) * PS_ + kt * 16 + bcolb) * 2);
                uint32_t bh0, bh1, bl0, bl1;
                ldsm_x2(bh0, bh1, adr);
                ldsm_x2(bl0, bl1, adr + (OFF_KL - OFF_KH));
                mma16816(acc[j], qa[0][kt], bh0, bh1);
                mma16816(acc[j], qa[0][kt], bl0, bl1);
                mma16816(acc[j], qa[1][kt], bh0, bh1);
            }
        }
    }

    // mask diagonal tiles, rowsum z (kept in registers), convert -> A-frags
    const int m0r = r0 + g4, m1r = m0r + 8;
    float z0 = 0.f, z1 = 0.f;
    uint32_t aB[2][8][4];
#pragma unroll
    for (int j = 0; j < 16; j++) {
        if (j < ntiles) {
            float c0 = acc[j][0], c1 = acc[j][1], c2 = acc[j][2], c3 = acc[j][3];
            if (j >= 2 * rt) {
                const int n0 = 8 * j + 2 * t4;
                c0 = (n0     <= m0r) ? c0 : 0.f;
                c1 = (n0 + 1 <= m0r) ? c1 : 0.f;
                c2 = (n0     <= m1r) ? c2 : 0.f;
                c3 = (n0 + 1 <= m1r) ? c3 : 0.f;
            }
            z0 += c0 + c1;
            z1 += c2 + c3;
            uint32_t h01, l01, h23, l23;
            tsplit2(c0, c1, h01, l01);
            tsplit2(c2, c3, h23, l23);
            const int kt2 = j >> 1, p = (j & 1) * 2;
            aB[0][kt2][p] = h01; aB[0][kt2][p + 1] = h23;
            aB[1][kt2][p] = l01; aB[1][kt2][p + 1] = l23;
        }
    }
    z0 += __shfl_xor_sync(0xffffffffu, z0, 1);
    z0 += __shfl_xor_sync(0xffffffffu, z0, 2);
    z1 += __shfl_xor_sync(0xffffffffu, z1, 1);
    z1 += __shfl_xor_sync(0xffffffffu, z1, 2);

    // ---- Phase B: O = A V (K truncated by causality) ------------------------
    float o[8][4];
#pragma unroll
    for (int nt = 0; nt < 8; nt++)
#pragma unroll
        for (int t = 0; t < 4; t++) o[nt][t] = 0.f;

#pragma unroll
    for (int kt = 0; kt < 8; kt++) {
        if (kt <= rt) {
#pragma unroll
            for (int nt = 0; nt < 8; nt++) {
                const uint32_t adr = sb + OFF_VH +
                    (uint32_t)(((kt * 16 + vrow) * PS_ + nt * 8) * 2);
                uint32_t bh0, bh1, bl0, bl1;
                ldsm_x2t(bh0, bh1, adr);
                ldsm_x2t(bl0, bl1, adr + (OFF_VL - OFF_VH));
                mma16816(o[nt], aB[0][kt], bh0, bh1);
                mma16816(o[nt], aB[0][kt], bl0, bl1);
                mma16816(o[nt], aB[1][kt], bh0, bh1);
            }
        }
    }

    // ---- Phase C: O += Qf S_prev (+ 9th tile -> qdk from Ksum column) -------
    float o9[4] = {0.f, 0.f, 0.f, 0.f};
#pragma unroll
    for (int kt = 0; kt < 4; kt++) {
#pragma unroll
        for (int nt = 0; nt < 9; nt++) {
            const uint32_t adr = sb + OFF_SH +
                (uint32_t)(((kt * 16 + vrow) * PS_ + nt * 8) * 2);
            uint32_t bh0, bh1, bl0, bl1;
            ldsm_x2t(bh0, bh1, adr);
            ldsm_x2t(bl0, bl1, adr + (OFF_SL - OFF_SH));
            float* dst = (nt < 8) ? o[nt] : o9;
            mma16816(dst, qa[0][kt], bh0, bh1);
            mma16816(dst, qa[0][kt], bl0, bl1);
            mma16816(dst, qa[1][kt], bh0, bh1);
        }
    }

    // ---- epilogue: z = rowsum(A) + Qf.Ksum_prev; divide, store ---------------
    {
        const float qdk_a = __shfl_sync(0xffffffffu, o9[0], g4 * 4);
        const float qdk_b = __shfl_sync(0xffffffffu, o9[2], g4 * 4);
        const float inva = 1.f / (z0 + qdk_a + EPS_);
        const float invb = 1.f / (z1 + qdk_b + EPS_);
        const long ob0 = gbase + (long)m0r * HD_;
        const long ob1 = gbase + (long)m1r * HD_;
#pragma unroll
        for (int nt = 0; nt < 8; nt++) {
            const int n = nt * 8 + 2 * t4;
            *reinterpret_cast<float2*>(&out[ob0 + n]) =
                make_float2(o[nt][0] * inva, o[nt][1] * inva);
            *reinterpret_cast<float2*>(&out[ob1 + n]) =
                make_float2(o[nt][2] * invb, o[nt][3] * invb);
        }
    }
}

// ---------------------------------------------------------------------------
extern "C" void kernel_launch(void* const* d_in, const int* in_sizes, int n_in,
                              void* d_out, int out_size) {
    const float* q = (const float*)d_in[0];
    const float* k = (const float*)d_in[1];
    const float* v = (const float*)d_in[2];
    float* out = (float*)d_out;

    cudaFuncSetAttribute(la_pass1, cudaFuncAttributeMaxDynamicSharedMemorySize, SMEM1);
    cudaFuncSetAttribute(la_pass3, cudaFuncAttributeMaxDynamicSharedMemorySize, SMEM3);

    la_pass1<<<BH_ * NC_, 256, SMEM1>>>(k, v);
    la_pass2<<<BH_ * 8, 256>>>();
    la_pass3<<<BH_ * NC_, 256, SMEM3>>>(q, k, v, out);
}

// round 5
// speedup vs baseline: 2.5029x; 1.1833x over previous
#include <cuda_runtime.h>
#include <cuda_bf16.h>
#include <cstdint>

// Causal linear attention (elu+1), chunked, mma.sync bf16 hi/lo (fp32-emulated).
// q,k,v: [B=4, L=2048, H=16, D=64] fp32 -> out [B,L,H,64] fp32.

namespace {
constexpr int B_ = 4, L_ = 2048, H_ = 16, D_ = 64, M_ = 64;
constexpr int C_ = 128;
constexpr int NC_ = L_ / C_;   // 16
constexpr int BH_ = B_ * H_;   // 64
constexpr float EPS_ = 1e-6f;
constexpr int HD_ = H_ * D_;   // 1024
constexpr int PS_ = 72;        // padded row stride (bf16) -> 144B, conflict-free LDSM

constexpr int SZT = C_ * PS_ * 2;   // 18432 B per 128-row bf16 tile

// pass3 smem: S tiles ALIAS Q tiles (Q smem dead once qa frags are in regs)
constexpr int OFF_KH = 0;
constexpr int OFF_KL = OFF_KH + SZT;
constexpr int OFF_VH = OFF_KL + SZT;
constexpr int OFF_VL = OFF_VH + SZT;
constexpr int OFF_QH = OFF_VL + SZT;
constexpr int OFF_QL = OFF_QH + SZT;
constexpr int OFF_SH = OFF_QH;             // alias
constexpr int OFF_SL = OFF_QL;             // alias
constexpr int SMEM3  = 6 * SZT;            // 110,592 B -> 2 blocks/SM

// pass1 smem
constexpr int P1_KH = 0;
constexpr int P1_KL = P1_KH + SZT;
constexpr int P1_VH = P1_KL + SZT;
constexpr int P1_VL = P1_VH + SZT;
constexpr int P1_RED = P1_VL + SZT;        // 4*64 floats
constexpr int SMEM1  = P1_RED + 1024;      // 74,752 B -> 3 blocks/SM
}

__device__ float g_KV[(size_t)BH_ * NC_ * D_ * M_];
__device__ float g_Ks[BH_ * NC_ * D_];

__device__ __forceinline__ float fmap(float x) { return x > 0.f ? x + 1.f : __expf(x); }

__device__ __forceinline__ uint32_t smem_u32(const void* p) {
    uint32_t a;
    asm("{ .reg .u64 t; cvta.to.shared.u64 t, %1; cvt.u32.u64 %0, t; }" : "=r"(a) : "l"(p));
    return a;
}
// truncation-based hi/lo split of a float pair -> packed bf16x2 (lo lane = f0)
__device__ __forceinline__ void tsplit2(float f0, float f1, uint32_t& h, uint32_t& l) {
    const uint32_t u0 = __float_as_uint(f0), u1 = __float_as_uint(f1);
    asm("prmt.b32 %0, %1, %2, 0x7632;" : "=r"(h) : "r"(u0), "r"(u1));
    const float r0 = f0 - __uint_as_float(u0 & 0xffff0000u);
    const float r1 = f1 - __uint_as_float(u1 & 0xffff0000u);
    asm("cvt.rn.bf16x2.f32 %0, %1, %2;" : "=r"(l) : "f"(r1), "f"(r0));
}
__device__ __forceinline__ void tsplit4(const float* f, uint2& hi, uint2& lo) {
    tsplit2(f[0], f[1], hi.x, lo.x);
    tsplit2(f[2], f[3], hi.y, lo.y);
}

__device__ __forceinline__ void ldsm_x4(uint32_t* r, uint32_t addr) {
    asm volatile("ldmatrix.sync.aligned.m8n8.x4.shared.b16 {%0,%1,%2,%3}, [%4];"
                 : "=r"(r[0]), "=r"(r[1]), "=r"(r[2]), "=r"(r[3]) : "r"(addr));
}
__device__ __forceinline__ void ldsm_x4t(uint32_t* r, uint32_t addr) {
    asm volatile("ldmatrix.sync.aligned.m8n8.x4.trans.shared.b16 {%0,%1,%2,%3}, [%4];"
                 : "=r"(r[0]), "=r"(r[1]), "=r"(r[2]), "=r"(r[3]) : "r"(addr));
}
__device__ __forceinline__ void ldsm_x2(uint32_t& b0, uint32_t& b1, uint32_t addr) {
    asm volatile("ldmatrix.sync.aligned.m8n8.x2.shared.b16 {%0,%1}, [%2];"
                 : "=r"(b0), "=r"(b1) : "r"(addr));
}
__device__ __forceinline__ void ldsm_x2t(uint32_t& b0, uint32_t& b1, uint32_t addr) {
    asm volatile("ldmatrix.sync.aligned.m8n8.x2.trans.shared.b16 {%0,%1}, [%2];"
                 : "=r"(b0), "=r"(b1) : "r"(addr));
}
__device__ __forceinline__ void mma16816(float* c, const uint32_t* a, uint32_t b0, uint32_t b1) {
    asm volatile("mma.sync.aligned.m16n8k16.row.col.f32.bf16.bf16.f32 "
                 "{%0,%1,%2,%3}, {%4,%5,%6,%7}, {%8,%9}, {%0,%1,%2,%3};"
                 : "+f"(c[0]), "+f"(c[1]), "+f"(c[2]), "+f"(c[3])
                 : "r"(a[0]), "r"(a[1]), "r"(a[2]), "r"(a[3]), "r"(b0), "r"(b1));
}

// ---------------------------------------------------------------------------
// Pass 1: per-chunk KV = Kf^T V via mma.sync. grid = BH*NC, block = 256.
// ---------------------------------------------------------------------------
__global__ __launch_bounds__(256) void la_pass1(const float* __restrict__ k,
                                                const float* __restrict__ v) {
    extern __shared__ char smem[];
    const uint32_t sb = smem_u32(smem);
    const int tid = threadIdx.x;
    const int wid = tid >> 5, lane = tid & 31;

    const int blk = blockIdx.x;
    const int bh = blk / NC_, c = blk % NC_;
    const int b = bh / H_, h = bh % H_;
    const long gbase = (((long)b * L_ + (long)c * C_) * H_ + h) * D_;

    // P0: load k,v chunk; fmap(k); trunc-split -> padded smem tiles (batched MLP)
#pragma unroll 4
    for (int it = 0; it < 8; it++) {
        const int i = tid + it * 256;
        const int l = i >> 4, d4 = (i & 15) * 4;
        const long g = gbase + (long)l * HD_ + d4;
        const int so = (l * PS_ + d4) * 2;
        uint2 hi, lo;

        const float4 kk = *reinterpret_cast<const float4*>(&k[g]);
        const float4 vv = *reinterpret_cast<const float4*>(&v[g]);

        float fk[4] = {fmap(kk.x), fmap(kk.y), fmap(kk.z), fmap(kk.w)};
        tsplit4(fk, hi, lo);
        *reinterpret_cast<uint2*>(smem + P1_KH + so) = hi;
        *reinterpret_cast<uint2*>(smem + P1_KL + so) = lo;

        float fv[4] = {vv.x, vv.y, vv.z, vv.w};
        tsplit4(fv, hi, lo);
        *reinterpret_cast<uint2*>(smem + P1_VH + so) = hi;
        *reinterpret_cast<uint2*>(smem + P1_VL + so) = lo;
    }
    __syncthreads();

    // MMA: warp wid owns n-tile (m columns 8*wid..8*wid+8); M=64 (d), K=128 (l)
    const int g4 = lane >> 2, t4 = lane & 3;
    const int vrow = (lane & 7) + ((lane >> 3) & 1) * 8;           // B x2.trans row
    const int asrow = (lane & 7) + ((lane >> 4) & 1) * 8;          // A x4.trans src row
    const int ascol = ((lane >> 3) & 1) * 8;                       // A x4.trans src col

    float acc[4][4];
#pragma unroll
    for (int mt = 0; mt < 4; mt++)
#pragma unroll
        for (int t = 0; t < 4; t++) acc[mt][t] = 0.f;

#pragma unroll
    for (int kt = 0; kt < 8; kt++) {
        uint32_t bh0, bh1, bl0, bl1;
        const uint32_t adrV = sb + P1_VH + (uint32_t)(((kt * 16 + vrow) * PS_ + wid * 8) * 2);
        ldsm_x2t(bh0, bh1, adrV);
        ldsm_x2t(bl0, bl1, adrV + (P1_VL - P1_VH));
#pragma unroll
        for (int mt = 0; mt < 4; mt++) {
            uint32_t ah[4], al[4];
            const uint32_t adrK = sb + P1_KH +
                (uint32_t)(((kt * 16 + asrow) * PS_ + mt * 16 + ascol) * 2);
            ldsm_x4t(ah, adrK);
            ldsm_x4t(al, adrK + (P1_KL - P1_KH));
            mma16816(acc[mt], ah, bh0, bh1);
            mma16816(acc[mt], ah, bl0, bl1);
            mma16816(acc[mt], al, bh0, bh1);
        }
    }

    // write KV [d][m] fp32
    {
        const size_t ob = (size_t)blk * (D_ * M_);
        const int m = wid * 8 + 2 * t4;
#pragma unroll
        for (int mt = 0; mt < 4; mt++) {
            const int d0 = mt * 16 + g4;
            *reinterpret_cast<float2*>(&g_KV[ob + (size_t)d0 * M_ + m]) =
                make_float2(acc[mt][0], acc[mt][1]);
            *reinterpret_cast<float2*>(&g_KV[ob + (size_t)(d0 + 8) * M_ + m]) =
                make_float2(acc[mt][2], acc[mt][3]);
        }
    }

    // Ksum[d] = sum_l Kf[l][d]
    {
        float* red = reinterpret_cast<float*>(smem + P1_RED);
        const int part = tid >> 6, d = tid & 63;
        const __nv_bfloat16* kh = reinterpret_cast<const __nv_bfloat16*>(smem + P1_KH);
        const __nv_bfloat16* kl = reinterpret_cast<const __nv_bfloat16*>(smem + P1_KL);
        float s = 0.f;
#pragma unroll 8
        for (int l = part * 32; l < part * 32 + 32; l++) {
            const int so = l * PS_ + d;
            s += __bfloat162float(kh[so]) + __bfloat162float(kl[so]);
        }
        red[part * 64 + d] = s;
        __syncthreads();
        if (tid < 64)
            g_Ks[blk * D_ + tid] = red[tid] + red[64 + tid] + red[128 + tid] + red[192 + tid];
    }
}

// ---------------------------------------------------------------------------
// Pass 2: exclusive prefix over chunks (register-pipelined, MLP=16).
// grid = BH*8, block = 256.
// ---------------------------------------------------------------------------
__global__ __launch_bounds__(256) void la_pass2() {
    const int bh = blockIdx.x >> 3;
    const int sub = blockIdx.x & 7;
    const int e0 = sub * 512;

#pragma unroll
    for (int r = 0; r < 2; r++) {
        const int e = e0 + threadIdx.x + r * 256;
        float vals[NC_];
#pragma unroll
        for (int c = 0; c < NC_; c++)
            vals[c] = g_KV[(size_t)(bh * NC_ + c) * (D_ * M_) + e];
        float run = 0.f;
#pragma unroll
        for (int c = 0; c < NC_; c++) {
            const float t = vals[c];
            g_KV[(size_t)(bh * NC_ + c) * (D_ * M_) + e] = run;
            run += t;
        }
    }
    if (sub == 0 && threadIdx.x < D_) {
        const int e = threadIdx.x;
        float vals[NC_];
#pragma unroll
        for (int c = 0; c < NC_; c++)
            vals[c] = g_Ks[(bh * NC_ + c) * D_ + e];
        float run = 0.f;
#pragma unroll
        for (int c = 0; c < NC_; c++) {
            const float t = vals[c];
            g_Ks[(bh * NC_ + c) * D_ + e] = run;
            run += t;
        }
    }
}

// ---------------------------------------------------------------------------
// Pass 3: mma.sync chunk attention. grid = BH*NC, block = 256 (8 warps).
// Warp w owns row-tile rt = (w<4 ? w : 11-w) -> per-SMSP work balanced.
// S_prev tiles alias the Q tiles (written after qa frags are register-resident).
// ---------------------------------------------------------------------------
__global__ __launch_bounds__(256) void la_pass3(const float* __restrict__ q,
                                                const float* __restrict__ k,
                                                const float* __restrict__ v,
                                                float* __restrict__ out) {
    extern __shared__ char smem[];
    const uint32_t sb = smem_u32(smem);
    const int tid = threadIdx.x;
    const int wid = tid >> 5, lane = tid & 31;

    const int blk = blockIdx.x;
    const int bh = blk / NC_, c = blk % NC_;
    const int b = bh / H_, h = bh % H_;
    const long gbase = (((long)b * L_ + (long)c * C_) * H_ + h) * D_;

    // ---- P0: load chunk, fmap, trunc-split -> padded smem tiles ------------
#pragma unroll 4
    for (int it = 0; it < 8; it++) {
        const int i = tid + it * 256;
        const int l = i >> 4, d4 = (i & 15) * 4;
        const long g = gbase + (long)l * HD_ + d4;
        const int so = (l * PS_ + d4) * 2;
        uint2 hi, lo;

        const float4 qv = *reinterpret_cast<const float4*>(&q[g]);
        const float4 kv = *reinterpret_cast<const float4*>(&k[g]);
        const float4 vv = *reinterpret_cast<const float4*>(&v[g]);

        float fq[4] = {fmap(qv.x), fmap(qv.y), fmap(qv.z), fmap(qv.w)};
        tsplit4(fq, hi, lo);
        *reinterpret_cast<uint2*>(smem + OFF_QH + so) = hi;
        *reinterpret_cast<uint2*>(smem + OFF_QL + so) = lo;

        float fk[4] = {fmap(kv.x), fmap(kv.y), fmap(kv.z), fmap(kv.w)};
        tsplit4(fk, hi, lo);
        *reinterpret_cast<uint2*>(smem + OFF_KH + so) = hi;
        *reinterpret_cast<uint2*>(smem + OFF_KL + so) = lo;

        float fv[4] = {vv.x, vv.y, vv.z, vv.w};
        tsplit4(fv, hi, lo);
        *reinterpret_cast<uint2*>(smem + OFF_VH + so) = hi;
        *reinterpret_cast<uint2*>(smem + OFF_VL + so) = lo;
    }
    __syncthreads();

    const int rt = (wid < 4) ? wid : 11 - wid;    // SMSP-balanced row-tile
    const int r0 = rt * 16;
    const int g4 = lane >> 2, t4 = lane & 3;

    const int arow = (lane & 7) + ((lane >> 3) & 1) * 8;   // x4 row
    const int acolb = (lane >> 4) * 8;                     // x4 col block
    const int brow = lane & 7;                             // x2 row
    const int bcolb = ((lane >> 3) & 1) * 8;               // x2 col block
    const int vrow = (lane & 7) + ((lane >> 3) & 1) * 8;   // x2.trans k-row

    // ---- qa frags to registers (Q smem dead afterwards) --------------------
    uint32_t qa[2][4][4];
#pragma unroll
    for (int kt = 0; kt < 4; kt++) {
        const uint32_t aH = sb + OFF_QH + (uint32_t)(((r0 + arow) * PS_ + kt * 16 + acolb) * 2);
        ldsm_x4(qa[0][kt], aH);
        ldsm_x4(qa[1][kt], aH + (OFF_QL - OFF_QH));
    }
    __syncthreads();   // all warps hold qa -> Q smem reusable

    // ---- S_prev tile [64][64] + Ksum_prev at column 64 -> aliased region ----
    {
        const size_t spb = (size_t)blk * (D_ * M_);
#pragma unroll
        for (int ii = 0; ii < 4; ii++) {
            const int i = tid + ii * 256;
            const int d = i >> 4, m4 = (i & 15) * 4;
            const float4 sv = *reinterpret_cast<const float4*>(&g_KV[spb + (size_t)d * M_ + m4]);
            float fs[4] = {sv.x, sv.y, sv.z, sv.w};
            uint2 hi, lo;
            tsplit4(fs, hi, lo);
            const int so = (d * PS_ + m4) * 2;
            *reinterpret_cast<uint2*>(smem + OFF_SH + so) = hi;
            *reinterpret_cast<uint2*>(smem + OFF_SL + so) = lo;
        }
        if (tid < D_) {
            const float ks = g_Ks[blk * D_ + tid];
            uint32_t hh, ll;
            tsplit2(ks, 0.f, hh, ll);
            const int so = (tid * PS_ + 64) * 2;
            *reinterpret_cast<uint2*>(smem + OFF_SH + so) = make_uint2(hh, 0u);
            *reinterpret_cast<uint2*>(smem + OFF_SH + so + 8) = make_uint2(0u, 0u);
            *reinterpret_cast<uint2*>(smem + OFF_SL + so) = make_uint2(ll, 0u);
            *reinterpret_cast<uint2*>(smem + OFF_SL + so + 8) = make_uint2(0u, 0u);
        }
    }

    // ---- Phase A: A = Qf Kf^T (causal tiles only) ---------------------------
    const int ntiles = 2 * rt + 2;
    float acc[16][4];
#pragma unroll
    for (int j = 0; j < 16; j++)
#pragma unroll
        for (int t = 0; t < 4; t++) acc[j][t] = 0.f;

#pragma unroll
    for (int j = 0; j < 16; j++) {
        if (j < ntiles) {
#pragma unroll
            for (int kt = 0; kt < 4; kt++) {
                const uint32_t adr = sb + OFF_KH +
                    (uint32_t)(((8 * j + brow) * PS_ + kt * 16 + bcolb) * 2);
                uint32_t bh0, bh1, bl0, bl1;
                ldsm_x2(bh0, bh1, adr);
                ldsm_x2(bl0, bl1, adr + (OFF_KL - OFF_KH));
                mma16816(acc[j], qa[0][kt], bh0, bh1);
                mma16816(acc[j], qa[0][kt], bl0, bl1);
                mma16816(acc[j], qa[1][kt], bh0, bh1);
            }
        }
    }

    // mask diagonal tiles, rowsum z (registers), convert -> A-frags
    const int m0r = r0 + g4, m1r = m0r + 8;
    float z0 = 0.f, z1 = 0.f;
    uint32_t aB[2][8][4];
#pragma unroll
    for (int j = 0; j < 16; j++) {
        if (j < ntiles) {
            float c0 = acc[j][0], c1 = acc[j][1], c2 = acc[j][2], c3 = acc[j][3];
            if (j >= 2 * rt) {
                const int n0 = 8 * j + 2 * t4;
                c0 = (n0     <= m0r) ? c0 : 0.f;
                c1 = (n0 + 1 <= m0r) ? c1 : 0.f;
                c2 = (n0     <= m1r) ? c2 : 0.f;
                c3 = (n0 + 1 <= m1r) ? c3 : 0.f;
            }
            z0 += c0 + c1;
            z1 += c2 + c3;
            uint32_t h01, l01, h23, l23;
            tsplit2(c0, c1, h01, l01);
            tsplit2(c2, c3, h23, l23);
            const int kt2 = j >> 1, p = (j & 1) * 2;
            aB[0][kt2][p] = h01; aB[0][kt2][p + 1] = h23;
            aB[1][kt2][p] = l01; aB[1][kt2][p + 1] = l23;
        }
    }
    z0 += __shfl_xor_sync(0xffffffffu, z0, 1);
    z0 += __shfl_xor_sync(0xffffffffu, z0, 2);
    z1 += __shfl_xor_sync(0xffffffffu, z1, 1);
    z1 += __shfl_xor_sync(0xffffffffu, z1, 2);

    // ---- Phase B: O = A V (K truncated by causality) ------------------------
    float o[8][4];
#pragma unroll
    for (int nt = 0; nt < 8; nt++)
#pragma unroll
        for (int t = 0; t < 4; t++) o[nt][t] = 0.f;

#pragma unroll
    for (int kt = 0; kt < 8; kt++) {
        if (kt <= rt) {
#pragma unroll
            for (int nt = 0; nt < 8; nt++) {
                const uint32_t adr = sb + OFF_VH +
                    (uint32_t)(((kt * 16 + vrow) * PS_ + nt * 8) * 2);
                uint32_t bh0, bh1, bl0, bl1;
                ldsm_x2t(bh0, bh1, adr);
                ldsm_x2t(bl0, bl1, adr + (OFF_VL - OFF_VH));
                mma16816(o[nt], aB[0][kt], bh0, bh1);
                mma16816(o[nt], aB[0][kt], bl0, bl1);
                mma16816(o[nt], aB[1][kt], bh0, bh1);
            }
        }
    }
    __syncthreads();   // S tiles (aliased) fully written before phase C reads

    // ---- Phase C: O += Qf S_prev (+ 9th tile -> qdk from Ksum column) -------
    float o9[4] = {0.f, 0.f, 0.f, 0.f};
#pragma unroll
    for (int kt = 0; kt < 4; kt++) {
#pragma unroll
        for (int nt = 0; nt < 9; nt++) {
            const uint32_t adr = sb + OFF_SH +
                (uint32_t)(((kt * 16 + vrow) * PS_ + nt * 8) * 2);
            uint32_t bh0, bh1, bl0, bl1;
            ldsm_x2t(bh0, bh1, adr);
            ldsm_x2t(bl0, bl1, adr + (OFF_SL - OFF_SH));
            float* dst = (nt < 8) ? o[nt] : o9;
            mma16816(dst, qa[0][kt], bh0, bh1);
            mma16816(dst, qa[0][kt], bl0, bl1);
            mma16816(dst, qa[1][kt], bh0, bh1);
        }
    }

    // ---- epilogue: z = rowsum(A) + Qf.Ksum_prev; divide, store ---------------
    {
        const float qdk_a = __shfl_sync(0xffffffffu, o9[0], g4 * 4);
        const float qdk_b = __shfl_sync(0xffffffffu, o9[2], g4 * 4);
        const float inva = 1.f / (z0 + qdk_a + EPS_);
        const float invb = 1.f / (z1 + qdk_b + EPS_);
        const long ob0 = gbase + (long)m0r * HD_;
        const long ob1 = gbase + (long)m1r * HD_;
#pragma unroll
        for (int nt = 0; nt < 8; nt++) {
            const int n = nt * 8 + 2 * t4;
            *reinterpret_cast<float2*>(&out[ob0 + n]) =
                make_float2(o[nt][0] * inva, o[nt][1] * inva);
            *reinterpret_cast<float2*>(&out[ob1 + n]) =
                make_float2(o[nt][2] * invb, o[nt][3] * invb);
        }
    }
}

// ---------------------------------------------------------------------------
extern "C" void kernel_launch(void* const* d_in, const int* in_sizes, int n_in,
                              void* d_out, int out_size) {
    const float* q = (const float*)d_in[0];
    const float* k = (const float*)d_in[1];
    const float* v = (const float*)d_in[2];
    float* out = (float*)d_out;

    cudaFuncSetAttribute(la_pass1, cudaFuncAttributeMaxDynamicSharedMemorySize, SMEM1);
    cudaFuncSetAttribute(la_pass3, cudaFuncAttributeMaxDynamicSharedMemorySize, SMEM3);

    la_pass1<<<BH_ * NC_, 256, SMEM1>>>(k, v);
    la_pass2<<<BH_ * 8, 256>>>();
    la_pass3<<<BH_ * NC_, 256, SMEM3>>>(q, k, v, out);
}

// round 6
// speedup vs baseline: 3.5413x; 1.4149x over previous
#include <cuda_runtime.h>
#include <cuda_bf16.h>
#include <cstdint>

// Causal linear attention (elu+1), chunked, mma.sync bf16 hi/lo (fp32-emulated).
// q,k,v: [B=4, L=2048, H=16, D=64] fp32 -> out [B,L,H,64] fp32.

namespace {
constexpr int B_ = 4, L_ = 2048, H_ = 16, D_ = 64, M_ = 64;
constexpr int C_ = 128;
constexpr int NC_ = L_ / C_;   // 16
constexpr int BH_ = B_ * H_;   // 64
constexpr float EPS_ = 1e-6f;
constexpr int HD_ = H_ * D_;   // 1024
constexpr int PS_ = 72;        // padded row stride (bf16) -> 144B, conflict-free LDSM

constexpr int SZT = C_ * PS_ * 2;   // 18432 B per 128-row bf16 tile

// pass3 smem: S tiles ALIAS Q tiles (Q smem dead once qa frags are in regs)
constexpr int OFF_KH = 0;
constexpr int OFF_KL = OFF_KH + SZT;
constexpr int OFF_VH = OFF_KL + SZT;
constexpr int OFF_VL = OFF_VH + SZT;
constexpr int OFF_QH = OFF_VL + SZT;
constexpr int OFF_QL = OFF_QH + SZT;
constexpr int OFF_SH = OFF_QH;             // alias
constexpr int OFF_SL = OFF_QL;             // alias
constexpr int SMEM3  = 6 * SZT;            // 110,592 B -> 2 blocks/SM

// pass1 smem
constexpr int P1_KH = 0;
constexpr int P1_KL = P1_KH + SZT;
constexpr int P1_VH = P1_KL + SZT;
constexpr int P1_VL = P1_VH + SZT;
constexpr int P1_RED = P1_VL + SZT;        // 4*64 floats
constexpr int SMEM1  = P1_RED + 1024;      // 74,752 B -> 3 blocks/SM
}

__device__ float g_KV[(size_t)BH_ * NC_ * D_ * M_];
__device__ float g_Ks[BH_ * NC_ * D_];

__device__ __forceinline__ float fmap(float x) { return x > 0.f ? x + 1.f : __expf(x); }

__device__ __forceinline__ uint32_t smem_u32(const void* p) {
    uint32_t a;
    asm("{ .reg .u64 t; cvta.to.shared.u64 t, %1; cvt.u32.u64 %0, t; }" : "=r"(a) : "l"(p));
    return a;
}
// truncation-based hi/lo split of a float pair -> packed bf16x2 (lo lane = f0)
__device__ __forceinline__ void tsplit2(float f0, float f1, uint32_t& h, uint32_t& l) {
    const uint32_t u0 = __float_as_uint(f0), u1 = __float_as_uint(f1);
    asm("prmt.b32 %0, %1, %2, 0x7632;" : "=r"(h) : "r"(u0), "r"(u1));
    const float r0 = f0 - __uint_as_float(u0 & 0xffff0000u);
    const float r1 = f1 - __uint_as_float(u1 & 0xffff0000u);
    asm("cvt.rn.bf16x2.f32 %0, %1, %2;" : "=r"(l) : "f"(r1), "f"(r0));
}
__device__ __forceinline__ void tsplit4(const float* f, uint2& hi, uint2& lo) {
    tsplit2(f[0], f[1], hi.x, lo.x);
    tsplit2(f[2], f[3], hi.y, lo.y);
}

__device__ __forceinline__ void ldsm_x4(uint32_t* r, uint32_t addr) {
    asm volatile("ldmatrix.sync.aligned.m8n8.x4.shared.b16 {%0,%1,%2,%3}, [%4];"
                 : "=r"(r[0]), "=r"(r[1]), "=r"(r[2]), "=r"(r[3]) : "r"(addr));
}
__device__ __forceinline__ void ldsm_x4t(uint32_t* r, uint32_t addr) {
    asm volatile("ldmatrix.sync.aligned.m8n8.x4.trans.shared.b16 {%0,%1,%2,%3}, [%4];"
                 : "=r"(r[0]), "=r"(r[1]), "=r"(r[2]), "=r"(r[3]) : "r"(addr));
}
__device__ __forceinline__ void ldsm_x2t(uint32_t& b0, uint32_t& b1, uint32_t addr) {
    asm volatile("ldmatrix.sync.aligned.m8n8.x2.trans.shared.b16 {%0,%1}, [%2];"
                 : "=r"(b0), "=r"(b1) : "r"(addr));
}
__device__ __forceinline__ void mma16816(float* c, const uint32_t* a, uint32_t b0, uint32_t b1) {
    asm volatile("mma.sync.aligned.m16n8k16.row.col.f32.bf16.bf16.f32 "
                 "{%0,%1,%2,%3}, {%4,%5,%6,%7}, {%8,%9}, {%0,%1,%2,%3};"
                 : "+f"(c[0]), "+f"(c[1]), "+f"(c[2]), "+f"(c[3])
                 : "r"(a[0]), "r"(a[1]), "r"(a[2]), "r"(a[3]), "r"(b0), "r"(b1));
}

// ---------------------------------------------------------------------------
// Pass 1: per-chunk KV = Kf^T V via mma.sync. grid = BH*NC, block = 256.
// ---------------------------------------------------------------------------
__global__ __launch_bounds__(256) void la_pass1(const float* __restrict__ k,
                                                const float* __restrict__ v) {
    extern __shared__ char smem[];
    const uint32_t sb = smem_u32(smem);
    const int tid = threadIdx.x;
    const int wid = tid >> 5, lane = tid & 31;

    const int blk = blockIdx.x;
    const int bh = blk / NC_, c = blk % NC_;
    const int b = bh / H_, h = bh % H_;
    const long gbase = (((long)b * L_ + (long)c * C_) * H_ + h) * D_;

#pragma unroll 4
    for (int it = 0; it < 8; it++) {
        const int i = tid + it * 256;
        const int l = i >> 4, d4 = (i & 15) * 4;
        const long g = gbase + (long)l * HD_ + d4;
        const int so = (l * PS_ + d4) * 2;
        uint2 hi, lo;

        const float4 kk = *reinterpret_cast<const float4*>(&k[g]);
        const float4 vv = *reinterpret_cast<const float4*>(&v[g]);

        float fk[4] = {fmap(kk.x), fmap(kk.y), fmap(kk.z), fmap(kk.w)};
        tsplit4(fk, hi, lo);
        *reinterpret_cast<uint2*>(smem + P1_KH + so) = hi;
        *reinterpret_cast<uint2*>(smem + P1_KL + so) = lo;

        float fv[4] = {vv.x, vv.y, vv.z, vv.w};
        tsplit4(fv, hi, lo);
        *reinterpret_cast<uint2*>(smem + P1_VH + so) = hi;
        *reinterpret_cast<uint2*>(smem + P1_VL + so) = lo;
    }
    __syncthreads();

    const int g4 = lane >> 2, t4 = lane & 3;
    const int vrow = (lane & 7) + ((lane >> 3) & 1) * 8;           // B x2.trans row
    const int asrow = (lane & 7) + ((lane >> 4) & 1) * 8;          // A x4.trans src row
    const int ascol = ((lane >> 3) & 1) * 8;                       // A x4.trans src col

    float acc[4][4];
#pragma unroll
    for (int mt = 0; mt < 4; mt++)
#pragma unroll
        for (int t = 0; t < 4; t++) acc[mt][t] = 0.f;

#pragma unroll
    for (int kt = 0; kt < 8; kt++) {
        uint32_t bh0, bh1, bl0, bl1;
        const uint32_t adrV = sb + P1_VH + (uint32_t)(((kt * 16 + vrow) * PS_ + wid * 8) * 2);
        ldsm_x2t(bh0, bh1, adrV);
        ldsm_x2t(bl0, bl1, adrV + (P1_VL - P1_VH));
#pragma unroll
        for (int mt = 0; mt < 4; mt++) {
            uint32_t ah[4], al[4];
            const uint32_t adrK = sb + P1_KH +
                (uint32_t)(((kt * 16 + asrow) * PS_ + mt * 16 + ascol) * 2);
            ldsm_x4t(ah, adrK);
            ldsm_x4t(al, adrK + (P1_KL - P1_KH));
            mma16816(acc[mt], ah, bh0, bh1);
            mma16816(acc[mt], ah, bl0, bl1);
            mma16816(acc[mt], al, bh0, bh1);
        }
    }

    {
        const size_t ob = (size_t)blk * (D_ * M_);
        const int m = wid * 8 + 2 * t4;
#pragma unroll
        for (int mt = 0; mt < 4; mt++) {
            const int d0 = mt * 16 + g4;
            *reinterpret_cast<float2*>(&g_KV[ob + (size_t)d0 * M_ + m]) =
                make_float2(acc[mt][0], acc[mt][1]);
            *reinterpret_cast<float2*>(&g_KV[ob + (size_t)(d0 + 8) * M_ + m]) =
                make_float2(acc[mt][2], acc[mt][3]);
        }
    }

    {
        float* red = reinterpret_cast<float*>(smem + P1_RED);
        const int part = tid >> 6, d = tid & 63;
        const __nv_bfloat16* kh = reinterpret_cast<const __nv_bfloat16*>(smem + P1_KH);
        const __nv_bfloat16* kl = reinterpret_cast<const __nv_bfloat16*>(smem + P1_KL);
        float s = 0.f;
#pragma unroll 8
        for (int l = part * 32; l < part * 32 + 32; l++) {
            const int so = l * PS_ + d;
            s += __bfloat162float(kh[so]) + __bfloat162float(kl[so]);
        }
        red[part * 64 + d] = s;
        __syncthreads();
        if (tid < 64)
            g_Ks[blk * D_ + tid] = red[tid] + red[64 + tid] + red[128 + tid] + red[192 + tid];
    }
}

// ---------------------------------------------------------------------------
// Pass 2: exclusive prefix over chunks (register-pipelined, MLP=16).
// ---------------------------------------------------------------------------
__global__ __launch_bounds__(256) void la_pass2() {
    const int bh = blockIdx.x >> 3;
    const int sub = blockIdx.x & 7;
    const int e0 = sub * 512;

#pragma unroll
    for (int r = 0; r < 2; r++) {
        const int e = e0 + threadIdx.x + r * 256;
        float vals[NC_];
#pragma unroll
        for (int c = 0; c < NC_; c++)
            vals[c] = g_KV[(size_t)(bh * NC_ + c) * (D_ * M_) + e];
        float run = 0.f;
#pragma unroll
        for (int c = 0; c < NC_; c++) {
            const float t = vals[c];
            g_KV[(size_t)(bh * NC_ + c) * (D_ * M_) + e] = run;
            run += t;
        }
    }
    if (sub == 0 && threadIdx.x < D_) {
        const int e = threadIdx.x;
        float vals[NC_];
#pragma unroll
        for (int c = 0; c < NC_; c++)
            vals[c] = g_Ks[(bh * NC_ + c) * D_ + e];
        float run = 0.f;
#pragma unroll
        for (int c = 0; c < NC_; c++) {
            const float t = vals[c];
            g_Ks[(bh * NC_ + c) * D_ + e] = run;
            run += t;
        }
    }
}

// ---------------------------------------------------------------------------
// Pass 3: fused A/B mma.sync chunk attention. grid = BH*NC, block = 256.
// Warp w owns row-tile rt = (w<4 ? w : 11-w) (SMSP balanced).
// Phase A tile-pair j2 is converted to an A-frag and immediately consumed by
// phase B k-step j2 -> no persistent A storage, ~110 live regs, 2 blocks/SM.
// ---------------------------------------------------------------------------
__global__ __launch_bounds__(256, 2) void la_pass3(const float* __restrict__ q,
                                                   const float* __restrict__ k,
                                                   const float* __restrict__ v,
                                                   float* __restrict__ out) {
    extern __shared__ char smem[];
    const uint32_t sb = smem_u32(smem);
    const int tid = threadIdx.x;
    const int wid = tid >> 5, lane = tid & 31;

    const int blk = blockIdx.x;
    const int bh = blk / NC_, c = blk % NC_;
    const int b = bh / H_, h = bh % H_;
    const long gbase = (((long)b * L_ + (long)c * C_) * H_ + h) * D_;

    // ---- P0: load chunk, fmap, trunc-split -> padded smem tiles ------------
#pragma unroll 4
    for (int it = 0; it < 8; it++) {
        const int i = tid + it * 256;
        const int l = i >> 4, d4 = (i & 15) * 4;
        const long g = gbase + (long)l * HD_ + d4;
        const int so = (l * PS_ + d4) * 2;
        uint2 hi, lo;

        const float4 qv = *reinterpret_cast<const float4*>(&q[g]);
        const float4 kv = *reinterpret_cast<const float4*>(&k[g]);
        const float4 vv = *reinterpret_cast<const float4*>(&v[g]);

        float fq[4] = {fmap(qv.x), fmap(qv.y), fmap(qv.z), fmap(qv.w)};
        tsplit4(fq, hi, lo);
        *reinterpret_cast<uint2*>(smem + OFF_QH + so) = hi;
        *reinterpret_cast<uint2*>(smem + OFF_QL + so) = lo;

        float fk[4] = {fmap(kv.x), fmap(kv.y), fmap(kv.z), fmap(kv.w)};
        tsplit4(fk, hi, lo);
        *reinterpret_cast<uint2*>(smem + OFF_KH + so) = hi;
        *reinterpret_cast<uint2*>(smem + OFF_KL + so) = lo;

        float fv[4] = {vv.x, vv.y, vv.z, vv.w};
        tsplit4(fv, hi, lo);
        *reinterpret_cast<uint2*>(smem + OFF_VH + so) = hi;
        *reinterpret_cast<uint2*>(smem + OFF_VL + so) = lo;
    }
    __syncthreads();

    const int rt = (wid < 4) ? wid : 11 - wid;    // SMSP-balanced row-tile
    const int r0 = rt * 16;
    const int g4 = lane >> 2, t4 = lane & 3;

    const int arow = (lane & 7) + ((lane >> 3) & 1) * 8;   // A x4 row
    const int acolb = (lane >> 4) * 8;                     // A x4 col block
    const int krow = (lane & 7) + ((lane >> 4) & 1) * 8;   // K x4: bit4 -> row+8 (tile pair)
    const int kcol = ((lane >> 3) & 1) * 8;                // K x4: bit3 -> k-half
    const int vrow = (lane & 7) + ((lane >> 3) & 1) * 8;   // V/S x4t: bit3 -> k-half
    const int vcol = ((lane >> 4) & 1) * 8;                // V/S x4t: bit4 -> n-tile

    // ---- qa frags to registers (Q smem dead afterwards) --------------------
    uint32_t qa[2][4][4];
#pragma unroll
    for (int kt = 0; kt < 4; kt++) {
        const uint32_t aH = sb + OFF_QH + (uint32_t)(((r0 + arow) * PS_ + kt * 16 + acolb) * 2);
        ldsm_x4(qa[0][kt], aH);
        ldsm_x4(qa[1][kt], aH + (OFF_QL - OFF_QH));
    }
    __syncthreads();   // all warps hold qa -> Q smem reusable

    // ---- S_prev tile [64][64] + Ksum_prev at column 64 -> aliased region ----
    {
        const size_t spb = (size_t)blk * (D_ * M_);
#pragma unroll
        for (int ii = 0; ii < 4; ii++) {
            const int i = tid + ii * 256;
            const int d = i >> 4, m4 = (i & 15) * 4;
            const float4 sv = *reinterpret_cast<const float4*>(&g_KV[spb + (size_t)d * M_ + m4]);
            float fs[4] = {sv.x, sv.y, sv.z, sv.w};
            uint2 hi, lo;
            tsplit4(fs, hi, lo);
            const int so = (d * PS_ + m4) * 2;
            *reinterpret_cast<uint2*>(smem + OFF_SH + so) = hi;
            *reinterpret_cast<uint2*>(smem + OFF_SL + so) = lo;
        }
        if (tid < D_) {
            const float ks = g_Ks[blk * D_ + tid];
            uint32_t hh, ll;
            tsplit2(ks, 0.f, hh, ll);
            const int so = (tid * PS_ + 64) * 2;
            *reinterpret_cast<uint2*>(smem + OFF_SH + so) = make_uint2(hh, 0u);
            *reinterpret_cast<uint2*>(smem + OFF_SH + so + 8) = make_uint2(0u, 0u);
            *reinterpret_cast<uint2*>(smem + OFF_SL + so) = make_uint2(ll, 0u);
            *reinterpret_cast<uint2*>(smem + OFF_SL + so + 8) = make_uint2(0u, 0u);
        }
    }

    // ---- Fused phase A+B: per k-chunk j2, A-tiles -> frag -> O += A.V ------
    const int m0r = r0 + g4, m1r = m0r + 8;
    float z0 = 0.f, z1 = 0.f;
    float o[8][4];
#pragma unroll
    for (int nt = 0; nt < 8; nt++)
#pragma unroll
        for (int t = 0; t < 4; t++) o[nt][t] = 0.f;

    for (int j2 = 0; j2 <= rt; j2++) {
        // A tiles j=2*j2, 2*j2+1 : acc2[tile][4]
        float acc2[2][4] = {{0.f, 0.f, 0.f, 0.f}, {0.f, 0.f, 0.f, 0.f}};
#pragma unroll
        for (int kt = 0; kt < 4; kt++) {
            uint32_t kh[4], kl[4];
            const uint32_t adr = sb + OFF_KH +
                (uint32_t)(((16 * j2 + krow) * PS_ + kt * 16 + kcol) * 2);
            ldsm_x4(kh, adr);
            ldsm_x4(kl, adr + (OFF_KL - OFF_KH));
            mma16816(acc2[0], qa[0][kt], kh[0], kh[1]);
            mma16816(acc2[0], qa[0][kt], kl[0], kl[1]);
            mma16816(acc2[0], qa[1][kt], kh[0], kh[1]);
            mma16816(acc2[1], qa[0][kt], kh[2], kh[3]);
            mma16816(acc2[1], qa[0][kt], kl[2], kl[3]);
            mma16816(acc2[1], qa[1][kt], kh[2], kh[3]);
        }

        // mask diagonal pair, rowsum z, convert to A-frag (aH/aL)
        uint32_t aH[4], aL[4];
#pragma unroll
        for (int tl = 0; tl < 2; tl++) {
            float c0 = acc2[tl][0], c1 = acc2[tl][1], c2 = acc2[tl][2], c3 = acc2[tl][3];
            if (j2 == rt) {
                const int n0 = 16 * rt + tl * 8 + 2 * t4;
                c0 = (n0     <= m0r) ? c0 : 0.f;
                c1 = (n0 + 1 <= m0r) ? c1 : 0.f;
                c2 = (n0     <= m1r) ? c2 : 0.f;
                c3 = (n0 + 1 <= m1r) ? c3 : 0.f;
            }
            z0 += c0 + c1;
            z1 += c2 + c3;
            tsplit2(c0, c1, aH[tl * 2], aL[tl * 2]);
            tsplit2(c2, c3, aH[tl * 2 + 1], aL[tl * 2 + 1]);
        }

        // O += A_j2 . V[16*j2 .. 16*j2+16][:]
#pragma unroll
        for (int nt2 = 0; nt2 < 4; nt2++) {
            uint32_t vh[4], vl[4];
            const uint32_t adr = sb + OFF_VH +
                (uint32_t)(((16 * j2 + vrow) * PS_ + nt2 * 16 + vcol) * 2);
            ldsm_x4t(vh, adr);
            ldsm_x4t(vl, adr + (OFF_VL - OFF_VH));
            mma16816(o[2 * nt2],     aH, vh[0], vh[1]);
            mma16816(o[2 * nt2],     aH, vl[0], vl[1]);
            mma16816(o[2 * nt2],     aL, vh[0], vh[1]);
            mma16816(o[2 * nt2 + 1], aH, vh[2], vh[3]);
            mma16816(o[2 * nt2 + 1], aH, vl[2], vl[3]);
            mma16816(o[2 * nt2 + 1], aL, vh[2], vh[3]);
        }
    }
    z0 += __shfl_xor_sync(0xffffffffu, z0, 1);
    z0 += __shfl_xor_sync(0xffffffffu, z0, 2);
    z1 += __shfl_xor_sync(0xffffffffu, z1, 1);
    z1 += __shfl_xor_sync(0xffffffffu, z1, 2);

    __syncthreads();   // S tiles (aliased) fully written before phase C reads

    // ---- Phase C: O += Qf S_prev (+ 9th tile -> qdk from Ksum column) -------
    float o9[4] = {0.f, 0.f, 0.f, 0.f};
#pragma unroll
    for (int kt = 0; kt < 4; kt++) {
#pragma unroll
        for (int nt2 = 0; nt2 < 4; nt2++) {
            uint32_t vh[4], vl[4];
            const uint32_t adr = sb + OFF_SH +
                (uint32_t)(((kt * 16 + vrow) * PS_ + nt2 * 16 + vcol) * 2);
            ldsm_x4t(vh, adr);
            ldsm_x4t(vl, adr + (OFF_SL - OFF_SH));
            mma16816(o[2 * nt2],     qa[0][kt], vh[0], vh[1]);
            mma16816(o[2 * nt2],     qa[0][kt], vl[0], vl[1]);
            mma16816(o[2 * nt2],     qa[1][kt], vh[0], vh[1]);
            mma16816(o[2 * nt2 + 1], qa[0][kt], vh[2], vh[3]);
            mma16816(o[2 * nt2 + 1], qa[0][kt], vl[2], vl[3]);
            mma16816(o[2 * nt2 + 1], qa[1][kt], vh[2], vh[3]);
        }
        // 9th n-tile (Ksum column 64)
        {
            uint32_t bh0, bh1, bl0, bl1;
            const uint32_t adr = sb + OFF_SH +
                (uint32_t)(((kt * 16 + vrow) * PS_ + 64) * 2);
            ldsm_x2t(bh0, bh1, adr);
            ldsm_x2t(bl0, bl1, adr + (OFF_SL - OFF_SH));
            mma16816(o9, qa[0][kt], bh0, bh1);
            mma16816(o9, qa[0][kt], bl0, bl1);
            mma16816(o9, qa[1][kt], bh0, bh1);
        }
    }

    // ---- epilogue: z = rowsum(A) + Qf.Ksum_prev; divide, store ---------------
    {
        const float qdk_a = __shfl_sync(0xffffffffu, o9[0], g4 * 4);
        const float qdk_b = __shfl_sync(0xffffffffu, o9[2], g4 * 4);
        const float inva = 1.f / (z0 + qdk_a + EPS_);
        const float invb = 1.f / (z1 + qdk_b + EPS_);
        const long ob0 = gbase + (long)m0r * HD_;
        const long ob1 = gbase + (long)m1r * HD_;
#pragma unroll
        for (int nt = 0; nt < 8; nt++) {
            const int n = nt * 8 + 2 * t4;
            *reinterpret_cast<float2*>(&out[ob0 + n]) =
                make_float2(o[nt][0] * inva, o[nt][1] * inva);
            *reinterpret_cast<float2*>(&out[ob1 + n]) =
                make_float2(o[nt][2] * invb, o[nt][3] * invb);
        }
    }
}

// ---------------------------------------------------------------------------
extern "C" void kernel_launch(void* const* d_in, const int* in_sizes, int n_in,
                              void* d_out, int out_size) {
    const float* q = (const float*)d_in[0];
    const float* k = (const float*)d_in[1];
    const float* v = (const float*)d_in[2];
    float* out = (float*)d_out;

    cudaFuncSetAttribute(la_pass1, cudaFuncAttributeMaxDynamicSharedMemorySize, SMEM1);
    cudaFuncSetAttribute(la_pass3, cudaFuncAttributeMaxDynamicSharedMemorySize, SMEM3);

    la_pass1<<<BH_ * NC_, 256, SMEM1>>>(k, v);
    la_pass2<<<BH_ * 8, 256>>>();
    la_pass3<<<BH_ * NC_, 256, SMEM3>>>(q, k, v, out);
}

// round 7
// speedup vs baseline: 4.2098x; 1.1888x over previous
#include <cuda_runtime.h>
#include <cuda_bf16.h>
#include <cstdint>

// Causal linear attention (elu+1), SINGLE fused kernel (chunk KV aggregate +
// decoupled-lookback prefix + intra-chunk attention), mma.sync bf16 hi/lo.
// q,k,v: [B=4, L=2048, H=16, D=64] fp32 -> out [B,L,H,64] fp32.

namespace {
constexpr int B_ = 4, L_ = 2048, H_ = 16, D_ = 64, M_ = 64;
constexpr int C_ = 128;
constexpr int NC_ = L_ / C_;   // 16
constexpr int BH_ = B_ * H_;   // 64
constexpr int NBLK_ = BH_ * NC_;  // 1024
constexpr float EPS_ = 1e-6f;
constexpr int HD_ = H_ * D_;   // 1024
constexpr int PS_ = 72;        // padded row stride (bf16) -> 144B, conflict-free LDSM

constexpr int SZT = C_ * PS_ * 2;   // 18432 B per 128-row bf16 tile

// smem: S tiles / scratch ALIAS Q tiles (Q dead once qa frags in regs)
constexpr int OFF_KH = 0;
constexpr int OFF_KL = OFF_KH + SZT;
constexpr int OFF_VH = OFF_KL + SZT;
constexpr int OFF_VL = OFF_VH + SZT;
constexpr int OFF_QH = OFF_VL + SZT;
constexpr int OFF_QL = OFF_QH + SZT;
constexpr int OFF_SH = OFF_QH;             // alias
constexpr int OFF_SL = OFF_QL;             // alias
constexpr int SMEM3  = 6 * SZT;            // 110,592 B -> 2 blocks/SM

constexpr int AGG_N = D_ * M_ + D_;        // 4160 floats: KV + Ksum
}

__device__ float g_agg[NBLK_][AGG_N];
__device__ float g_inc[NBLK_][AGG_N];
__device__ int   g_flag[NBLK_];

__device__ __forceinline__ float fmap(float x) { return x > 0.f ? x + 1.f : __expf(x); }

__device__ __forceinline__ uint32_t smem_u32(const void* p) {
    uint32_t a;
    asm("{ .reg .u64 t; cvta.to.shared.u64 t, %1; cvt.u32.u64 %0, t; }" : "=r"(a) : "l"(p));
    return a;
}
__device__ __forceinline__ int ld_acquire(const int* p) {
    int v;
    asm volatile("ld.acquire.gpu.global.b32 %0, [%1];" : "=r"(v) : "l"(p) : "memory");
    return v;
}
__device__ __forceinline__ void st_release(int* p, int v) {
    asm volatile("st.release.gpu.global.b32 [%0], %1;" :: "l"(p), "r"(v) : "memory");
}
// truncation-based hi/lo split of a float pair -> packed bf16x2 (lo lane = f0)
__device__ __forceinline__ void tsplit2(float f0, float f1, uint32_t& h, uint32_t& l) {
    const uint32_t u0 = __float_as_uint(f0), u1 = __float_as_uint(f1);
    asm("prmt.b32 %0, %1, %2, 0x7632;" : "=r"(h) : "r"(u0), "r"(u1));
    const float r0 = f0 - __uint_as_float(u0 & 0xffff0000u);
    const float r1 = f1 - __uint_as_float(u1 & 0xffff0000u);
    asm("cvt.rn.bf16x2.f32 %0, %1, %2;" : "=r"(l) : "f"(r1), "f"(r0));
}
__device__ __forceinline__ void tsplit4(const float* f, uint2& hi, uint2& lo) {
    tsplit2(f[0], f[1], hi.x, lo.x);
    tsplit2(f[2], f[3], hi.y, lo.y);
}

__device__ __forceinline__ void ldsm_x4(uint32_t* r, uint32_t addr) {
    asm volatile("ldmatrix.sync.aligned.m8n8.x4.shared.b16 {%0,%1,%2,%3}, [%4];"
                 : "=r"(r[0]), "=r"(r[1]), "=r"(r[2]), "=r"(r[3]) : "r"(addr));
}
__device__ __forceinline__ void ldsm_x4t(uint32_t* r, uint32_t addr) {
    asm volatile("ldmatrix.sync.aligned.m8n8.x4.trans.shared.b16 {%0,%1,%2,%3}, [%4];"
                 : "=r"(r[0]), "=r"(r[1]), "=r"(r[2]), "=r"(r[3]) : "r"(addr));
}
__device__ __forceinline__ void ldsm_x2t(uint32_t& b0, uint32_t& b1, uint32_t addr) {
    asm volatile("ldmatrix.sync.aligned.m8n8.x2.trans.shared.b16 {%0,%1}, [%2];"
                 : "=r"(b0), "=r"(b1) : "r"(addr));
}
__device__ __forceinline__ void mma16816(float* c, const uint32_t* a, uint32_t b0, uint32_t b1) {
    asm volatile("mma.sync.aligned.m16n8k16.row.col.f32.bf16.bf16.f32 "
                 "{%0,%1,%2,%3}, {%4,%5,%6,%7}, {%8,%9}, {%0,%1,%2,%3};"
                 : "+f"(c[0]), "+f"(c[1]), "+f"(c[2]), "+f"(c[3])
                 : "r"(a[0]), "r"(a[1]), "r"(a[2]), "r"(a[3]), "r"(b0), "r"(b1));
}

// ---------------------------------------------------------------------------
__global__ void la_clear() {
    const int i = blockIdx.x * 256 + threadIdx.x;
    if (i < NBLK_) g_flag[i] = 0;
}

// ---------------------------------------------------------------------------
// Fused kernel. grid = NBLK_ (blk = c*64 + bh), block = 256 (8 warps).
// ---------------------------------------------------------------------------
__global__ __launch_bounds__(256, 2) void la_fused(const float* __restrict__ q,
                                                   const float* __restrict__ k,
                                                   const float* __restrict__ v,
                                                   float* __restrict__ out) {
    extern __shared__ char smem[];
    const uint32_t sb = smem_u32(smem);
    const int tid = threadIdx.x;
    const int wid = tid >> 5, lane = tid & 31;

    const int blk = blockIdx.x;
    const int c = blk >> 6, bh = blk & 63;
    const int b = bh / H_, h = bh % H_;
    const long gbase = (((long)b * L_ + (long)c * C_) * H_ + h) * D_;

    // ---- P0: load chunk, fmap, trunc-split -> padded smem tiles ------------
#pragma unroll 4
    for (int it = 0; it < 8; it++) {
        const int i = tid + it * 256;
        const int l = i >> 4, d4 = (i & 15) * 4;
        const long g = gbase + (long)l * HD_ + d4;
        const int so = (l * PS_ + d4) * 2;
        uint2 hi, lo;

        const float4 qv = *reinterpret_cast<const float4*>(&q[g]);
        const float4 kv = *reinterpret_cast<const float4*>(&k[g]);
        const float4 vv = *reinterpret_cast<const float4*>(&v[g]);

        float fq[4] = {fmap(qv.x), fmap(qv.y), fmap(qv.z), fmap(qv.w)};
        tsplit4(fq, hi, lo);
        *reinterpret_cast<uint2*>(smem + OFF_QH + so) = hi;
        *reinterpret_cast<uint2*>(smem + OFF_QL + so) = lo;

        float fk[4] = {fmap(kv.x), fmap(kv.y), fmap(kv.z), fmap(kv.w)};
        tsplit4(fk, hi, lo);
        *reinterpret_cast<uint2*>(smem + OFF_KH + so) = hi;
        *reinterpret_cast<uint2*>(smem + OFF_KL + so) = lo;

        float fv[4] = {vv.x, vv.y, vv.z, vv.w};
        tsplit4(fv, hi, lo);
        *reinterpret_cast<uint2*>(smem + OFF_VH + so) = hi;
        *reinterpret_cast<uint2*>(smem + OFF_VL + so) = lo;
    }
    __syncthreads();

    const int rt = (wid < 4) ? wid : 11 - wid;    // SMSP-balanced row-tile
    const int r0 = rt * 16;
    const int g4 = lane >> 2, t4 = lane & 3;

    const int arow = (lane & 7) + ((lane >> 3) & 1) * 8;   // A x4 row
    const int acolb = (lane >> 4) * 8;                     // A x4 col block
    const int krow = (lane & 7) + ((lane >> 4) & 1) * 8;   // K x4 (phase A)
    const int kcol = ((lane >> 3) & 1) * 8;
    const int vrow = (lane & 7) + ((lane >> 3) & 1) * 8;   // V/S x4t + x2t row
    const int vcol = ((lane >> 4) & 1) * 8;
    const int asrow = (lane & 7) + ((lane >> 4) & 1) * 8;  // K x4t (aggregate MMA)
    const int ascol = ((lane >> 3) & 1) * 8;

    // ---- qa frags to registers (Q smem dead after the next sync) -----------
    uint32_t qa[2][4][4];
#pragma unroll
    for (int kt = 0; kt < 4; kt++) {
        const uint32_t aH = sb + OFF_QH + (uint32_t)(((r0 + arow) * PS_ + kt * 16 + acolb) * 2);
        ldsm_x4(qa[0][kt], aH);
        ldsm_x4(qa[1][kt], aH + (OFF_QL - OFF_QH));
    }

    // ---- chunk KV aggregate: KV = Kf^T V (warp wid -> m cols 8*wid) --------
    {
        float acc[4][4];
#pragma unroll
        for (int mt = 0; mt < 4; mt++)
#pragma unroll
            for (int t = 0; t < 4; t++) acc[mt][t] = 0.f;

#pragma unroll
        for (int kt = 0; kt < 8; kt++) {
            uint32_t bh0, bh1, bl0, bl1;
            const uint32_t adrV = sb + OFF_VH + (uint32_t)(((kt * 16 + vrow) * PS_ + wid * 8) * 2);
            ldsm_x2t(bh0, bh1, adrV);
            ldsm_x2t(bl0, bl1, adrV + (OFF_VL - OFF_VH));
#pragma unroll
            for (int mt = 0; mt < 4; mt++) {
                uint32_t ah[4], al[4];
                const uint32_t adrK = sb + OFF_KH +
                    (uint32_t)(((kt * 16 + asrow) * PS_ + mt * 16 + ascol) * 2);
                ldsm_x4t(ah, adrK);
                ldsm_x4t(al, adrK + (OFF_KL - OFF_KH));
                mma16816(acc[mt], ah, bh0, bh1);
                mma16816(acc[mt], ah, bl0, bl1);
                mma16816(acc[mt], al, bh0, bh1);
            }
        }
        __syncthreads();   // qa loads done -> Q area reusable as scratch

        // write aggregate KV
        const int m = wid * 8 + 2 * t4;
#pragma unroll
        for (int mt = 0; mt < 4; mt++) {
            const int d0 = mt * 16 + g4;
            *reinterpret_cast<float2*>(&g_agg[blk][d0 * M_ + m]) =
                make_float2(acc[mt][0], acc[mt][1]);
            *reinterpret_cast<float2*>(&g_agg[blk][(d0 + 8) * M_ + m]) =
                make_float2(acc[mt][2], acc[mt][3]);
        }
    }

    // ---- Ksum aggregate (reduction in aliased Q area) -----------------------
    float ksum_own = 0.f;
    {
        float* red = reinterpret_cast<float*>(smem + OFF_QH);
        const int part = tid >> 6, d = tid & 63;
        const __nv_bfloat16* kh = reinterpret_cast<const __nv_bfloat16*>(smem + OFF_KH);
        const __nv_bfloat16* kl = reinterpret_cast<const __nv_bfloat16*>(smem + OFF_KL);
        float s = 0.f;
#pragma unroll 8
        for (int l = part * 32; l < part * 32 + 32; l++) {
            const int so = l * PS_ + d;
            s += __bfloat162float(kh[so]) + __bfloat162float(kl[so]);
        }
        red[part * 64 + d] = s;
        __syncthreads();
        if (tid < 64) {
            ksum_own = red[tid] + red[64 + tid] + red[128 + tid] + red[192 + tid];
            g_agg[blk][D_ * M_ + tid] = ksum_own;
        }
    }
    __threadfence();
    __syncthreads();
    if (tid == 0) st_release(&g_flag[blk], (c == 0) ? 3 : 1);  // 3: inclusive in g_agg

    // ---- Fused phase A+B (intra-chunk; independent of predecessors) --------
    const int m0r = r0 + g4, m1r = m0r + 8;
    float z0 = 0.f, z1 = 0.f;
    float o[8][4];
#pragma unroll
    for (int nt = 0; nt < 8; nt++)
#pragma unroll
        for (int t = 0; t < 4; t++) o[nt][t] = 0.f;

    for (int j2 = 0; j2 <= rt; j2++) {
        float acc2[2][4] = {{0.f, 0.f, 0.f, 0.f}, {0.f, 0.f, 0.f, 0.f}};
#pragma unroll
        for (int kt = 0; kt < 4; kt++) {
            uint32_t kh[4], kl[4];
            const uint32_t adr = sb + OFF_KH +
                (uint32_t)(((16 * j2 + krow) * PS_ + kt * 16 + kcol) * 2);
            ldsm_x4(kh, adr);
            ldsm_x4(kl, adr + (OFF_KL - OFF_KH));
            mma16816(acc2[0], qa[0][kt], kh[0], kh[1]);
            mma16816(acc2[0], qa[0][kt], kl[0], kl[1]);
            mma16816(acc2[0], qa[1][kt], kh[0], kh[1]);
            mma16816(acc2[1], qa[0][kt], kh[2], kh[3]);
            mma16816(acc2[1], qa[0][kt], kl[2], kl[3]);
            mma16816(acc2[1], qa[1][kt], kh[2], kh[3]);
        }

        uint32_t aH[4], aL[4];
#pragma unroll
        for (int tl = 0; tl < 2; tl++) {
            float c0 = acc2[tl][0], c1 = acc2[tl][1], c2 = acc2[tl][2], c3 = acc2[tl][3];
            if (j2 == rt) {
                const int n0 = 16 * rt + tl * 8 + 2 * t4;
                c0 = (n0     <= m0r) ? c0 : 0.f;
                c1 = (n0 + 1 <= m0r) ? c1 : 0.f;
                c2 = (n0     <= m1r) ? c2 : 0.f;
                c3 = (n0 + 1 <= m1r) ? c3 : 0.f;
            }
            z0 += c0 + c1;
            z1 += c2 + c3;
            tsplit2(c0, c1, aH[tl * 2], aL[tl * 2]);
            tsplit2(c2, c3, aH[tl * 2 + 1], aL[tl * 2 + 1]);
        }

#pragma unroll
        for (int nt2 = 0; nt2 < 4; nt2++) {
            uint32_t vh[4], vl[4];
            const uint32_t adr = sb + OFF_VH +
                (uint32_t)(((16 * j2 + vrow) * PS_ + nt2 * 16 + vcol) * 2);
            ldsm_x4t(vh, adr);
            ldsm_x4t(vl, adr + (OFF_VL - OFF_VH));
            mma16816(o[2 * nt2],     aH, vh[0], vh[1]);
            mma16816(o[2 * nt2],     aH, vl[0], vl[1]);
            mma16816(o[2 * nt2],     aL, vh[0], vh[1]);
            mma16816(o[2 * nt2 + 1], aH, vh[2], vh[3]);
            mma16816(o[2 * nt2 + 1], aH, vl[2], vl[3]);
            mma16816(o[2 * nt2 + 1], aL, vh[2], vh[3]);
        }
    }
    z0 += __shfl_xor_sync(0xffffffffu, z0, 1);
    z0 += __shfl_xor_sync(0xffffffffu, z0, 2);
    z1 += __shfl_xor_sync(0xffffffffu, z1, 1);
    z1 += __shfl_xor_sync(0xffffffffu, z1, 2);

    // ---- lookback + phase C (skipped for c == 0) -----------------------------
    float o9[4] = {0.f, 0.f, 0.f, 0.f};
    if (c > 0) {
        float sp[16];
#pragma unroll
        for (int t = 0; t < 16; t++) sp[t] = 0.f;
        float ksum_prev = 0.f;

        volatile int* stat_s = reinterpret_cast<volatile int*>(smem + OFF_QH);
        int j = blk - BH_;
        while (true) {
            if (tid == 0) {
                int s;
                do { s = ld_acquire(&g_flag[j]); } while (s == 0);
                *stat_s = s;
            }
            __syncthreads();
            const int s = *stat_s;
            const float* src = (s == 2) ? g_inc[j] : g_agg[j];
#pragma unroll
            for (int ii = 0; ii < 4; ii++) {
                const float4 t = *reinterpret_cast<const float4*>(&src[4 * (tid + ii * 256)]);
                sp[ii * 4 + 0] += t.x; sp[ii * 4 + 1] += t.y;
                sp[ii * 4 + 2] += t.z; sp[ii * 4 + 3] += t.w;
            }
            if (tid < 64) ksum_prev += src[D_ * M_ + tid];
            __syncthreads();
            if (s >= 2) break;
            j -= BH_;
        }

        // publish inclusive (exclusive prefix + own aggregate)
        if (c < NC_ - 1) {
#pragma unroll
            for (int ii = 0; ii < 4; ii++) {
                const float4 t = *reinterpret_cast<const float4*>(&g_agg[blk][4 * (tid + ii * 256)]);
                *reinterpret_cast<float4*>(&g_inc[blk][4 * (tid + ii * 256)]) =
                    make_float4(sp[ii * 4 + 0] + t.x, sp[ii * 4 + 1] + t.y,
                                sp[ii * 4 + 2] + t.z, sp[ii * 4 + 3] + t.w);
            }
            if (tid < 64) g_inc[blk][D_ * M_ + tid] = ksum_prev + ksum_own;
            __threadfence();
            __syncthreads();
            if (tid == 0) st_release(&g_flag[blk], 2);
        } else {
            __syncthreads();
        }

        // split S_prev -> aliased S smem tiles + Ksum column 64
#pragma unroll
        for (int ii = 0; ii < 4; ii++) {
            const int i = tid + ii * 256;
            const int d = i >> 4, m4 = (i & 15) * 4;
            uint2 hi, lo;
            tsplit4(&sp[ii * 4], hi, lo);
            const int so = (d * PS_ + m4) * 2;
            *reinterpret_cast<uint2*>(smem + OFF_SH + so) = hi;
            *reinterpret_cast<uint2*>(smem + OFF_SL + so) = lo;
        }
        if (tid < D_) {
            uint32_t hh, ll;
            tsplit2(ksum_prev, 0.f, hh, ll);
            const int so = (tid * PS_ + 64) * 2;
            *reinterpret_cast<uint2*>(smem + OFF_SH + so) = make_uint2(hh, 0u);
            *reinterpret_cast<uint2*>(smem + OFF_SH + so + 8) = make_uint2(0u, 0u);
            *reinterpret_cast<uint2*>(smem + OFF_SL + so) = make_uint2(ll, 0u);
            *reinterpret_cast<uint2*>(smem + OFF_SL + so + 8) = make_uint2(0u, 0u);
        }
        __syncthreads();

        // phase C: O += Qf S_prev (+ 9th n-tile -> qdk)
#pragma unroll
        for (int kt = 0; kt < 4; kt++) {
#pragma unroll
            for (int nt2 = 0; nt2 < 4; nt2++) {
                uint32_t vh[4], vl[4];
                const uint32_t adr = sb + OFF_SH +
                    (uint32_t)(((kt * 16 + vrow) * PS_ + nt2 * 16 + vcol) * 2);
                ldsm_x4t(vh, adr);
                ldsm_x4t(vl, adr + (OFF_SL - OFF_SH));
                mma16816(o[2 * nt2],     qa[0][kt], vh[0], vh[1]);
                mma16816(o[2 * nt2],     qa[0][kt], vl[0], vl[1]);
                mma16816(o[2 * nt2],     qa[1][kt], vh[0], vh[1]);
                mma16816(o[2 * nt2 + 1], qa[0][kt], vh[2], vh[3]);
                mma16816(o[2 * nt2 + 1], qa[0][kt], vl[2], vl[3]);
                mma16816(o[2 * nt2 + 1], qa[1][kt], vh[2], vh[3]);
            }
            {
                uint32_t bh0, bh1, bl0, bl1;
                const uint32_t adr = sb + OFF_SH +
                    (uint32_t)(((kt * 16 + vrow) * PS_ + 64) * 2);
                ldsm_x2t(bh0, bh1, adr);
                ldsm_x2t(bl0, bl1, adr + (OFF_SL - OFF_SH));
                mma16816(o9, qa[0][kt], bh0, bh1);
                mma16816(o9, qa[0][kt], bl0, bl1);
                mma16816(o9, qa[1][kt], bh0, bh1);
            }
        }
    }

    // ---- epilogue: z = rowsum(A) + Qf.Ksum_prev; divide, store ---------------
    {
        const float qdk_a = __shfl_sync(0xffffffffu, o9[0], g4 * 4);
        const float qdk_b = __shfl_sync(0xffffffffu, o9[2], g4 * 4);
        const float inva = 1.f / (z0 + qdk_a + EPS_);
        const float invb = 1.f / (z1 + qdk_b + EPS_);
        const long ob0 = gbase + (long)m0r * HD_;
        const long ob1 = gbase + (long)m1r * HD_;
#pragma unroll
        for (int nt = 0; nt < 8; nt++) {
            const int n = nt * 8 + 2 * t4;
            *reinterpret_cast<float2*>(&out[ob0 + n]) =
                make_float2(o[nt][0] * inva, o[nt][1] * inva);
            *reinterpret_cast<float2*>(&out[ob1 + n]) =
                make_float2(o[nt][2] * invb, o[nt][3] * invb);
        }
    }
}

// ---------------------------------------------------------------------------
extern "C" void kernel_launch(void* const* d_in, const int* in_sizes, int n_in,
                              void* d_out, int out_size) {
    const float* q = (const float*)d_in[0];
    const float* k = (const float*)d_in[1];
    const float* v = (const float*)d_in[2];
    float* out = (float*)d_out;

    cudaFuncSetAttribute(la_fused, cudaFuncAttributeMaxDynamicSharedMemorySize, SMEM3);

    la_clear<<<(NBLK_ + 255) / 256, 256>>>();
    la_fused<<<NBLK_, 256, SMEM3>>>(q, k, v, out);
}